// round 1
// baseline (speedup 1.0000x reference)
#include <cuda_runtime.h>
#include <math.h>

#define NN 50000
#define NE 800000

// ---------------- scratch (static __device__ arrays: allowed) ----------------
static __device__ float d_deg[NN];
static __device__ float d_agg1[NN * 21];
static __device__ float d_mx[NN * 48];            // [mean(21)|x(21)|pad(6)]
static __device__ float d_wc1[256 * 48];
static __device__ float d_h1[(size_t)NN * 256];
static __device__ float d_wc2[256 * 256];
static __device__ float d_pq2[(size_t)NN * 256];  // [p(128)|q(128)]
static __device__ float d_agg2[(size_t)NN * 128];
static __device__ float d_h2[(size_t)NN * 128];
static __device__ float d_wc3[128 * 128];
static __device__ float d_pq3[(size_t)NN * 128];  // [p(64)|q(64)]
static __device__ float d_agg3[(size_t)NN * 64];
static __device__ float d_h3[(size_t)NN * 64];
static __device__ float d_xn[(size_t)NN * 64];
static __device__ float d_w1p[128 * 64];
static __device__ float d_b1p[128];
static __device__ float d_y1[(size_t)NN * 128];
static __device__ float d_m1[256 * 13 * 11 * 11];
static __device__ float d_m2[128 * 11 * 9 * 9];
static __device__ float d_mvec[64];
static __device__ float d_mnorm[64];
static __device__ float d_pmin[1024];
static __device__ float d_pmax[1024];
static __device__ float d_hstats[4];

// ---------------- small pack kernels ----------------
__global__ void k_pack1(const float* __restrict__ Wl, const float* __restrict__ Wr) {
    int i = blockIdx.x * blockDim.x + threadIdx.x;
    if (i >= 256 * 48) return;
    int n = i / 48, f = i % 48;
    float v = 0.f;
    if (f < 21) v = Wl[n * 21 + f];
    else if (f < 42) v = Wr[n * 21 + (f - 21)];
    d_wc1[i] = v;
}
__global__ void k_pack2(const float* __restrict__ Wl, const float* __restrict__ Wr) {
    int i = blockIdx.x * blockDim.x + threadIdx.x;
    if (i >= 256 * 256) return;
    int n = i / 256, f = i % 256;
    d_wc2[i] = (n < 128) ? Wl[n * 256 + f] : Wr[(n - 128) * 256 + f];
}
__global__ void k_pack3(const float* __restrict__ Wl, const float* __restrict__ Wr) {
    int i = blockIdx.x * blockDim.x + threadIdx.x;
    if (i >= 128 * 128) return;
    int n = i / 128, f = i % 128;
    d_wc3[i] = (n < 64) ? Wl[n * 128 + f] : Wr[(n - 64) * 128 + f];
}
__global__ void k_packW1(const float* __restrict__ W1, const float* __restrict__ b1) {
    int i = blockIdx.x * blockDim.x + threadIdx.x;
    if (i >= 128 * 64) return;
    int n = i / 64, f = i % 64;
    d_w1p[i] = (n < 64) ? W1[i] : 0.f;
    if (f == 0) d_b1p[n] = (n < 64) ? b1[n] : 0.f;
}

// ---------------- graph aggregation ----------------
__global__ void k_deg(const int* __restrict__ ei) {
    int e = blockIdx.x * blockDim.x + threadIdx.x;
    if (e < NE) atomicAdd(&d_deg[ei[NE + e]], 1.0f);
}
__global__ void k_agg1(const int* __restrict__ ei, const float* __restrict__ x) {
    int e = blockIdx.x * blockDim.x + threadIdx.x;
    if (e >= NE) return;
    int s = ei[e], d = ei[NE + e];
    const float* xs = x + (size_t)s * 21;
    float* ad = d_agg1 + (size_t)d * 21;
#pragma unroll
    for (int f = 0; f < 21; f++) atomicAdd(&ad[f], xs[f]);
}
__global__ void k_meanx(const float* __restrict__ x) {
    int i = blockIdx.x * blockDim.x + threadIdx.x;
    if (i >= NN * 48) return;
    int n = i / 48, f = i % 48;
    float v = 0.f;
    if (f < 21) {
        float c = fmaxf(d_deg[n], 1.0f);
        v = d_agg1[n * 21 + f] / c;
    } else if (f < 42) {
        v = x[(size_t)n * 21 + (f - 21)];
    }
    d_mx[i] = v;
}
// warp per edge, 128 features
__global__ void k_agg2(const int* __restrict__ ei) {
    int t = blockIdx.x * blockDim.x + threadIdx.x;
    int e = t >> 5, lane = t & 31;
    if (e >= NE) return;
    int s = ei[e], d = ei[NE + e];
    float4 v = *(const float4*)&d_pq2[(size_t)s * 256 + lane * 4];
    float* ad = &d_agg2[(size_t)d * 128 + lane * 4];
    atomicAdd(ad + 0, v.x); atomicAdd(ad + 1, v.y);
    atomicAdd(ad + 2, v.z); atomicAdd(ad + 3, v.w);
}
// half-warp per edge, 64 features
__global__ void k_agg3(const int* __restrict__ ei) {
    int t = blockIdx.x * blockDim.x + threadIdx.x;
    int e = t >> 4, part = t & 15;
    if (e >= NE) return;
    int s = ei[e], d = ei[NE + e];
    float4 v = *(const float4*)&d_pq3[(size_t)s * 128 + part * 4];
    float* ad = &d_agg3[(size_t)d * 64 + part * 4];
    atomicAdd(ad + 0, v.x); atomicAdd(ad + 1, v.y);
    atomicAdd(ad + 2, v.z); atomicAdd(ad + 3, v.w);
}
__global__ void k_comb2(const float* __restrict__ bl) {
    int i = blockIdx.x * blockDim.x + threadIdx.x;
    if (i >= NN * 128) return;
    int n = i >> 7, f = i & 127;
    float c = fmaxf(d_deg[n], 1.0f);
    float v = d_agg2[i] / c + bl[f] + d_pq2[(size_t)n * 256 + 128 + f];
    d_h2[i] = fmaxf(v, 0.f);
}
__global__ void k_comb3(const float* __restrict__ bl) {
    int i = blockIdx.x * blockDim.x + threadIdx.x;
    if (i >= NN * 64) return;
    int n = i >> 6, f = i & 63;
    float c = fmaxf(d_deg[n], 1.0f);
    d_h3[i] = d_agg3[i] / c + bl[f] + d_pq3[(size_t)n * 128 + 64 + f];
}

// ---------------- SGEMM: C[M,N] = A[M,K] * B[N,K]^T (+bias, relu) ----------------
// N multiple of 128, K multiple of 8, A rows padded/aligned to 16B.
__global__ void __launch_bounds__(256, 2) k_sgemm(
    const float* __restrict__ A, const float* __restrict__ B,
    float* __restrict__ C, int M, int N, int K,
    const float* __restrict__ bias, int relu) {
    __shared__ float As[8][128];
    __shared__ float Bs[8][128];
    int tid = threadIdx.x;
    int bm = blockIdx.y * 128;
    int bn = blockIdx.x * 128;
    int tx = tid & 15, ty = tid >> 4;
    int lr = tid >> 1;
    int lc = (tid & 1) * 4;
    float acc[8][8];
#pragma unroll
    for (int i = 0; i < 8; i++)
#pragma unroll
        for (int j = 0; j < 8; j++) acc[i][j] = 0.f;

    const float* Aptr = A + (size_t)(bm + lr) * K + lc;
    const float* Bptr = B + (size_t)(bn + lr) * K + lc;
    bool aval = (bm + lr) < M;

    for (int k0 = 0; k0 < K; k0 += 8) {
        float4 av = aval ? *(const float4*)(Aptr + k0) : make_float4(0.f, 0.f, 0.f, 0.f);
        float4 bv = *(const float4*)(Bptr + k0);
        As[lc + 0][lr] = av.x; As[lc + 1][lr] = av.y;
        As[lc + 2][lr] = av.z; As[lc + 3][lr] = av.w;
        Bs[lc + 0][lr] = bv.x; Bs[lc + 1][lr] = bv.y;
        Bs[lc + 2][lr] = bv.z; Bs[lc + 3][lr] = bv.w;
        __syncthreads();
#pragma unroll
        for (int kk = 0; kk < 8; kk++) {
            float4 a0 = *(const float4*)&As[kk][ty * 8];
            float4 a1 = *(const float4*)&As[kk][ty * 8 + 4];
            float4 b0 = *(const float4*)&Bs[kk][tx * 8];
            float4 b1 = *(const float4*)&Bs[kk][tx * 8 + 4];
            float a[8] = {a0.x, a0.y, a0.z, a0.w, a1.x, a1.y, a1.z, a1.w};
            float b[8] = {b0.x, b0.y, b0.z, b0.w, b1.x, b1.y, b1.z, b1.w};
#pragma unroll
            for (int i = 0; i < 8; i++)
#pragma unroll
                for (int j = 0; j < 8; j++) acc[i][j] += a[i] * b[j];
        }
        __syncthreads();
    }
#pragma unroll
    for (int i = 0; i < 8; i++) {
        int row = bm + ty * 8 + i;
        if (row >= M) continue;
#pragma unroll
        for (int j = 0; j < 8; j += 4) {
            int col = bn + tx * 8 + j;
            float4 v = make_float4(acc[i][j], acc[i][j + 1], acc[i][j + 2], acc[i][j + 3]);
            if (bias) {
                v.x += bias[col]; v.y += bias[col + 1];
                v.z += bias[col + 2]; v.w += bias[col + 3];
            }
            if (relu) {
                v.x = fmaxf(v.x, 0.f); v.y = fmaxf(v.y, 0.f);
                v.z = fmaxf(v.z, 0.f); v.w = fmaxf(v.w, 0.f);
            }
            *(float4*)&C[(size_t)row * N + col] = v;
        }
    }
}

// ---------------- map encoder ----------------
__global__ void k_conv1(const float* __restrict__ in, const float* __restrict__ w,
                        const float* __restrict__ b) {
    int idx = blockIdx.x * blockDim.x + threadIdx.x;
    if (idx >= 256 * 1573) return;
    int oc = idx / 1573, p = idx % 1573;
    int od = p / 121, r = p % 121, oh = r / 11, ow = r % 11;
    const float* wp = w + oc * 75;
    float acc = 0.f;
#pragma unroll
    for (int kd = 0; kd < 3; kd++)
#pragma unroll
        for (int kh = 0; kh < 5; kh++)
#pragma unroll
            for (int kw = 0; kw < 5; kw++)
                acc += in[(od + kd) * 225 + (oh + kh) * 15 + (ow + kw)] *
                       wp[kd * 25 + kh * 5 + kw];
    d_m1[idx] = fmaxf(acc + b[oc], 0.f);
}

// grid 128 (one oc per block), block 128; slab padded for float4 shared loads
__global__ void k_conv2(const float* __restrict__ w, const float* __restrict__ b) {
    __shared__ __align__(16) float slab[13 * 132];  // rows padded 11->12
    __shared__ float ws[32];
    int oc = blockIdx.x;
    int tid = threadIdx.x;
    int od = tid / 9, oh = tid % 9;
    bool act = tid < 99;
    float acc[9];
#pragma unroll
    for (int i = 0; i < 9; i++) acc[i] = 0.f;

    for (int ic = 0; ic < 256; ic++) {
        __syncthreads();
        const float* src = d_m1 + ic * 1573;
        for (int i = tid; i < 1573; i += 128) {
            int dd = i / 121, r = i % 121, hh = r / 11, ww = r % 11;
            slab[dd * 132 + hh * 12 + ww] = src[i];
        }
        if (tid < 27) ws[tid] = w[((size_t)oc * 256 + ic) * 27 + tid];
        __syncthreads();
        if (act) {
            float wr[27];
#pragma unroll
            for (int t = 0; t < 27; t++) wr[t] = ws[t];
#pragma unroll
            for (int kd = 0; kd < 3; kd++) {
#pragma unroll
                for (int kh = 0; kh < 3; kh++) {
                    const float* row = &slab[(od + kd) * 132 + (oh + kh) * 12];
                    float4 r0 = *(const float4*)(row);
                    float4 r1 = *(const float4*)(row + 4);
                    float4 r2 = *(const float4*)(row + 8);
                    float rv[12] = {r0.x, r0.y, r0.z, r0.w, r1.x, r1.y, r1.z, r1.w,
                                    r2.x, r2.y, r2.z, r2.w};
#pragma unroll
                    for (int kw = 0; kw < 3; kw++) {
                        float wv = wr[kd * 9 + kh * 3 + kw];
#pragma unroll
                        for (int ow = 0; ow < 9; ow++) acc[ow] += rv[ow + kw] * wv;
                    }
                }
            }
        }
    }
    if (act) {
        float bb = b[oc];
#pragma unroll
        for (int ow = 0; ow < 9; ow++)
            d_m2[(size_t)oc * 891 + od * 81 + oh * 9 + ow] = fmaxf(acc[ow] + bb, 0.f);
    }
}

__global__ void k_wm(const float* __restrict__ Wm, const float* __restrict__ bm) {
    __shared__ float red[256];
    int o = blockIdx.x;
    const float* wr = Wm + (size_t)o * 114048;
    float s = 0.f;
    for (int i = threadIdx.x * 4; i < 114048; i += 256 * 4) {
        float4 a = *(const float4*)(wr + i);
        float4 v = *(const float4*)(d_m2 + i);
        s += a.x * v.x + a.y * v.y + a.z * v.z + a.w * v.w;
    }
    red[threadIdx.x] = s;
    __syncthreads();
    for (int st = 128; st > 0; st >>= 1) {
        if (threadIdx.x < st) red[threadIdx.x] += red[threadIdx.x + st];
        __syncthreads();
    }
    if (threadIdx.x == 0) d_mvec[o] = red[0] + bm[o];
}

__global__ void k_mnorm() {
    __shared__ float smn[64], smx[64];
    int t = threadIdx.x;
    float v = d_mvec[t];
    smn[t] = v; smx[t] = v;
    __syncthreads();
    for (int st = 32; st > 0; st >>= 1) {
        if (t < st) {
            smn[t] = fminf(smn[t], smn[t + st]);
            smx[t] = fmaxf(smx[t], smx[t + st]);
        }
        __syncthreads();
    }
    float mn = smn[0], mx = smx[0];
    d_mnorm[t] = 0.65f * (v - mn) / (mx - mn);
}

// ---------------- h3 min/max ----------------
__global__ void k_hred1() {
    __shared__ float smn[256], smx[256];
    int tid = threadIdx.x;
    float mn = 3.4e38f, mx = -3.4e38f;
    for (size_t i = (size_t)blockIdx.x * 256 + tid; i < (size_t)NN * 64; i += (size_t)1024 * 256) {
        float v = d_h3[i];
        mn = fminf(mn, v); mx = fmaxf(mx, v);
    }
    smn[tid] = mn; smx[tid] = mx;
    __syncthreads();
    for (int st = 128; st > 0; st >>= 1) {
        if (tid < st) {
            smn[tid] = fminf(smn[tid], smn[tid + st]);
            smx[tid] = fmaxf(smx[tid], smx[tid + st]);
        }
        __syncthreads();
    }
    if (tid == 0) { d_pmin[blockIdx.x] = smn[0]; d_pmax[blockIdx.x] = smx[0]; }
}
__global__ void k_hred2() {
    __shared__ float smn[1024], smx[1024];
    int t = threadIdx.x;
    smn[t] = d_pmin[t]; smx[t] = d_pmax[t];
    __syncthreads();
    for (int st = 512; st > 0; st >>= 1) {
        if (t < st) {
            smn[t] = fminf(smn[t], smn[t + st]);
            smx[t] = fmaxf(smx[t], smx[t + st]);
        }
        __syncthreads();
    }
    if (t == 0) {
        float mn = smn[0], mx = smx[0];
        float a = 0.35f / (mx - mn);
        d_hstats[0] = a;
        d_hstats[1] = -mn * a;
    }
}

__global__ void k_xn() {
    int i4 = blockIdx.x * blockDim.x + threadIdx.x;
    if (i4 >= NN * 16) return;
    float a = d_hstats[0], c = d_hstats[1];
    int f4 = i4 & 15;
    float4 h = *(const float4*)&d_h3[(size_t)i4 * 4];
    float4 mn = *(const float4*)&d_mnorm[f4 * 4];
    float4 o;
    o.x = a * h.x + c + mn.x;
    o.y = a * h.y + c + mn.y;
    o.z = a * h.z + c + mn.z;
    o.w = a * h.w + c + mn.w;
    *(float4*)&d_xn[(size_t)i4 * 4] = o;
}

// ---------------- final 3-wide layer + softmax ----------------
__global__ void k_head(const float* __restrict__ W2, const float* __restrict__ b2,
                       float* __restrict__ out) {
    __shared__ float w2s[3][64];
    __shared__ float b2s[3];
    int tid = threadIdx.x;
    if (tid < 192) w2s[tid / 64][tid % 64] = W2[tid];
    if (tid < 3) b2s[tid] = b2[tid];
    __syncthreads();
    int i = blockIdx.x * blockDim.x + tid;
    if (i >= NN) return;
    const float* y = d_y1 + (size_t)i * 128;
    float s0 = b2s[0], s1 = b2s[1], s2 = b2s[2];
#pragma unroll
    for (int f = 0; f < 64; f += 4) {
        float4 v = *(const float4*)(y + f);
        s0 += v.x * w2s[0][f] + v.y * w2s[0][f + 1] + v.z * w2s[0][f + 2] + v.w * w2s[0][f + 3];
        s1 += v.x * w2s[1][f] + v.y * w2s[1][f + 1] + v.z * w2s[1][f + 2] + v.w * w2s[1][f + 3];
        s2 += v.x * w2s[2][f] + v.y * w2s[2][f + 1] + v.z * w2s[2][f + 2] + v.w * w2s[2][f + 3];
    }
    float m = fmaxf(s0, fmaxf(s1, s2));
    float e0 = expf(s0 - m), e1 = expf(s1 - m), e2 = expf(s2 - m);
    float inv = 1.f / (e0 + e1 + e2);
    out[(size_t)i * 3 + 0] = e0 * inv;
    out[(size_t)i * 3 + 1] = e1 * inv;
    out[(size_t)i * 3 + 2] = e2 * inv;
}

// ---------------- launch ----------------
extern "C" void kernel_launch(void* const* d_in, const int* in_sizes, int n_in,
                              void* d_out, int out_size) {
    (void)in_sizes; (void)n_in; (void)out_size;
    const float* node = (const float*)d_in[0];
    const int* ei = (const int*)d_in[1];
    const float* mapd = (const float*)d_in[2];
    const float* Wl1 = (const float*)d_in[3];
    const float* bl1 = (const float*)d_in[4];
    const float* Wr1 = (const float*)d_in[5];
    const float* Wl2 = (const float*)d_in[6];
    const float* bl2 = (const float*)d_in[7];
    const float* Wr2 = (const float*)d_in[8];
    const float* Wl3 = (const float*)d_in[9];
    const float* bl3 = (const float*)d_in[10];
    const float* Wr3 = (const float*)d_in[11];
    const float* k1 = (const float*)d_in[12];
    const float* cb1 = (const float*)d_in[13];
    const float* k2 = (const float*)d_in[14];
    const float* cb2 = (const float*)d_in[15];
    const float* Wm = (const float*)d_in[16];
    const float* bm = (const float*)d_in[17];
    const float* W1 = (const float*)d_in[18];
    const float* b1 = (const float*)d_in[19];
    const float* W2 = (const float*)d_in[20];
    const float* b2 = (const float*)d_in[21];
    float* out = (float*)d_out;

    void *p_deg, *p_agg1, *p_agg2, *p_agg3;
    void *p_mx, *p_wc1, *p_h1, *p_wc2, *p_pq2, *p_h2, *p_wc3, *p_pq3;
    void *p_xn, *p_w1p, *p_b1p, *p_y1;
    cudaGetSymbolAddress(&p_deg, d_deg);
    cudaGetSymbolAddress(&p_agg1, d_agg1);
    cudaGetSymbolAddress(&p_agg2, d_agg2);
    cudaGetSymbolAddress(&p_agg3, d_agg3);
    cudaGetSymbolAddress(&p_mx, d_mx);
    cudaGetSymbolAddress(&p_wc1, d_wc1);
    cudaGetSymbolAddress(&p_h1, d_h1);
    cudaGetSymbolAddress(&p_wc2, d_wc2);
    cudaGetSymbolAddress(&p_pq2, d_pq2);
    cudaGetSymbolAddress(&p_h2, d_h2);
    cudaGetSymbolAddress(&p_wc3, d_wc3);
    cudaGetSymbolAddress(&p_pq3, d_pq3);
    cudaGetSymbolAddress(&p_xn, d_xn);
    cudaGetSymbolAddress(&p_w1p, d_w1p);
    cudaGetSymbolAddress(&p_b1p, d_b1p);
    cudaGetSymbolAddress(&p_y1, d_y1);

    cudaMemsetAsync(p_deg, 0, NN * sizeof(float));
    cudaMemsetAsync(p_agg1, 0, (size_t)NN * 21 * sizeof(float));
    cudaMemsetAsync(p_agg2, 0, (size_t)NN * 128 * sizeof(float));
    cudaMemsetAsync(p_agg3, 0, (size_t)NN * 64 * sizeof(float));

    k_pack1<<<48, 256>>>(Wl1, Wr1);
    k_pack2<<<256, 256>>>(Wl2, Wr2);
    k_pack3<<<64, 256>>>(Wl3, Wr3);
    k_packW1<<<32, 256>>>(W1, b1);

    k_deg<<<(NE + 255) / 256, 256>>>(ei);
    k_agg1<<<(NE + 255) / 256, 256>>>(ei, node);
    k_meanx<<<(NN * 48 + 255) / 256, 256>>>(node);

    // layer 1: h1 = relu([mean|x] @ [Wl1|Wr1]^T + bl1)
    k_sgemm<<<dim3(2, 391), 256>>>((const float*)p_mx, (const float*)p_wc1,
                                   (float*)p_h1, NN, 256, 48, bl1, 1);
    // layer 2: project first, then aggregate p
    k_sgemm<<<dim3(2, 391), 256>>>((const float*)p_h1, (const float*)p_wc2,
                                   (float*)p_pq2, NN, 256, 256, (const float*)nullptr, 0);
    k_agg2<<<(NE * 32 + 255) / 256, 256>>>(ei);
    k_comb2<<<(NN * 128 + 255) / 256, 256>>>(bl2);
    // layer 3
    k_sgemm<<<dim3(1, 391), 256>>>((const float*)p_h2, (const float*)p_wc3,
                                   (float*)p_pq3, NN, 128, 128, (const float*)nullptr, 0);
    k_agg3<<<(NE * 16 + 255) / 256, 256>>>(ei);
    k_comb3<<<(NN * 64 + 255) / 256, 256>>>(bl3);

    // map encoder
    k_conv1<<<(256 * 1573 + 255) / 256, 256>>>(mapd, k1, cb1);
    k_conv2<<<128, 128>>>(k2, cb2);
    k_wm<<<64, 256>>>(Wm, bm);
    k_mnorm<<<1, 64>>>();

    // normalize h, combine, head
    k_hred1<<<1024, 256>>>();
    k_hred2<<<1, 1024>>>();
    k_xn<<<(NN * 16 + 255) / 256, 256>>>();
    k_sgemm<<<dim3(1, 391), 256>>>((const float*)p_xn, (const float*)p_w1p,
                                   (float*)p_y1, NN, 128, 64, (const float*)p_b1p, 1);
    k_head<<<(NN + 255) / 256, 256>>>(W2, b2, out);
}

// round 2
// speedup vs baseline: 1.4165x; 1.4165x over previous
#include <cuda_runtime.h>
#include <math.h>

#define NN 50000
#define NE 800000
#define NB1 196  // ceil(NN/256)

// ---------------- scratch ----------------
static __device__ int   d_cnt[NN];
static __device__ int   d_rowptr[NN + 1];
static __device__ int   d_cursor[NN];
static __device__ int   d_csrc[NE];
static __device__ int   d_part[256];
static __device__ float d_mx[NN * 48];            // [mean(21)|x(21)|pad(6)]
static __device__ float d_wc1[256 * 48];
static __device__ float d_h1[(size_t)NN * 256];
static __device__ float d_wc2[256 * 256];
static __device__ float d_pq2[(size_t)NN * 256];  // [p(128)|q(128)]
static __device__ float d_h2[(size_t)NN * 128];
static __device__ float d_wc3[128 * 128];
static __device__ float d_pq3[(size_t)NN * 128];  // [p(64)|q(64)]
static __device__ float d_h3[(size_t)NN * 64];
static __device__ float d_xn[(size_t)NN * 64];
static __device__ float d_w1p[128 * 64];
static __device__ float d_b1p[128];
static __device__ float d_y1[(size_t)NN * 128];
static __device__ float d_m1[256 * 13 * 11 * 11];
static __device__ float d_m2[128 * 11 * 9 * 9];
static __device__ float d_mvec[64];
static __device__ float d_mnorm[64];
static __device__ float d_pmin[1024];
static __device__ float d_pmax[1024];
static __device__ float d_hstats[4];

// ---------------- weight packing ----------------
__global__ void k_pack1(const float* __restrict__ Wl, const float* __restrict__ Wr) {
    int i = blockIdx.x * blockDim.x + threadIdx.x;
    if (i >= 256 * 48) return;
    int n = i / 48, f = i % 48;
    float v = 0.f;
    if (f < 21) v = Wl[n * 21 + f];
    else if (f < 42) v = Wr[n * 21 + (f - 21)];
    d_wc1[i] = v;
}
__global__ void k_pack2(const float* __restrict__ Wl, const float* __restrict__ Wr) {
    int i = blockIdx.x * blockDim.x + threadIdx.x;
    if (i >= 256 * 256) return;
    int n = i / 256, f = i % 256;
    d_wc2[i] = (n < 128) ? Wl[n * 256 + f] : Wr[(n - 128) * 256 + f];
}
__global__ void k_pack3(const float* __restrict__ Wl, const float* __restrict__ Wr) {
    int i = blockIdx.x * blockDim.x + threadIdx.x;
    if (i >= 128 * 128) return;
    int n = i / 128, f = i % 128;
    d_wc3[i] = (n < 64) ? Wl[n * 128 + f] : Wr[(n - 64) * 128 + f];
}
__global__ void k_packW1(const float* __restrict__ W1, const float* __restrict__ b1) {
    int i = blockIdx.x * blockDim.x + threadIdx.x;
    if (i >= 128 * 64) return;
    int n = i / 64, f = i % 64;
    d_w1p[i] = (n < 64) ? W1[i] : 0.f;
    if (f == 0) d_b1p[n] = (n < 64) ? b1[n] : 0.f;
}

// ---------------- CSR build ----------------
__global__ void k_degcnt(const int* __restrict__ ei) {
    int e = blockIdx.x * blockDim.x + threadIdx.x;
    if (e < NE) atomicAdd(&d_cnt[ei[NE + e]], 1);
}
__global__ void k_scan1() {
    __shared__ int sh[256];
    int t = threadIdx.x;
    int i = blockIdx.x * 256 + t;
    int v = (i < NN) ? d_cnt[i] : 0;
    sh[t] = v;
    __syncthreads();
#pragma unroll
    for (int off = 1; off < 256; off <<= 1) {
        int a = (t >= off) ? sh[t - off] : 0;
        __syncthreads();
        sh[t] += a;
        __syncthreads();
    }
    if (i < NN) d_rowptr[i] = sh[t] - v;  // block-local exclusive
    if (t == 255) d_part[blockIdx.x] = sh[255];
}
__global__ void k_scan2() {
    __shared__ int sh[256];
    int t = threadIdx.x;
    int v = (t < NB1) ? d_part[t] : 0;
    sh[t] = v;
    __syncthreads();
#pragma unroll
    for (int off = 1; off < 256; off <<= 1) {
        int a = (t >= off) ? sh[t - off] : 0;
        __syncthreads();
        sh[t] += a;
        __syncthreads();
    }
    if (t < NB1) d_part[t] = sh[t] - v;  // exclusive
}
__global__ void k_scan3() {
    int i = blockIdx.x * 256 + threadIdx.x;
    if (i < NN) {
        int r = d_rowptr[i] + d_part[blockIdx.x];
        d_rowptr[i] = r;
        d_cursor[i] = r;
    }
    if (i == 0) d_rowptr[NN] = NE;
}
__global__ void k_scatter(const int* __restrict__ ei) {
    int e = blockIdx.x * blockDim.x + threadIdx.x;
    if (e >= NE) return;
    int s = ei[e], d = ei[NE + e];
    int pos = atomicAdd(&d_cursor[d], 1);
    d_csrc[pos] = s;
}

// ---------------- CSR aggregation (no atomics) ----------------
// layer1: warp per node; lanes 0..20 = features; fused mean + x copy + pad
__global__ void k_aggA(const float* __restrict__ x) {
    int w = (blockIdx.x * blockDim.x + threadIdx.x) >> 5;
    int lane = threadIdx.x & 31;
    if (w >= NN) return;
    int beg = d_rowptr[w], end = d_rowptr[w + 1];
    float acc = 0.f;
    for (int e0 = beg; e0 < end; e0 += 32) {
        int cnt = min(32, end - e0);
        int idx = (e0 + lane < end) ? d_csrc[e0 + lane] : 0;
        for (int j = 0; j < cnt; j++) {
            int s = __shfl_sync(0xffffffffu, idx, j);
            if (lane < 21) acc += x[(size_t)s * 21 + lane];
        }
    }
    float inv = 1.f / fmaxf((float)(end - beg), 1.0f);
    if (lane < 21) {
        d_mx[(size_t)w * 48 + lane] = acc * inv;
        d_mx[(size_t)w * 48 + 21 + lane] = x[(size_t)w * 21 + lane];
    } else if (lane < 27) {
        d_mx[(size_t)w * 48 + 21 + lane] = 0.f;  // pad 42..47
    }
}
// layer2: warp per node, 128 feats as 32 x float4; fused mean+bias+residual+relu
__global__ void k_aggB(const float* __restrict__ bl) {
    int w = (blockIdx.x * blockDim.x + threadIdx.x) >> 5;
    int lane = threadIdx.x & 31;
    if (w >= NN) return;
    int beg = d_rowptr[w], end = d_rowptr[w + 1];
    const float4* pq = (const float4*)d_pq2;  // row = 64 float4
    float4 acc = make_float4(0.f, 0.f, 0.f, 0.f);
#pragma unroll 4
    for (int e = beg; e < end; e++) {
        int s = __ldg(&d_csrc[e]);
        float4 v = pq[(size_t)s * 64 + lane];
        acc.x += v.x; acc.y += v.y; acc.z += v.z; acc.w += v.w;
    }
    float inv = 1.f / fmaxf((float)(end - beg), 1.0f);
    float4 q = pq[(size_t)w * 64 + 32 + lane];
    float4 b = ((const float4*)bl)[lane];
    float4 o;
    o.x = fmaxf(acc.x * inv + b.x + q.x, 0.f);
    o.y = fmaxf(acc.y * inv + b.y + q.y, 0.f);
    o.z = fmaxf(acc.z * inv + b.z + q.z, 0.f);
    o.w = fmaxf(acc.w * inv + b.w + q.w, 0.f);
    ((float4*)d_h2)[(size_t)w * 32 + lane] = o;
}
// layer3: 16 lanes per node, 64 feats as 16 x float4; fused, no relu
__global__ void k_aggC(const float* __restrict__ bl) {
    int g = (blockIdx.x * blockDim.x + threadIdx.x) >> 4;
    int lane = threadIdx.x & 15;
    if (g >= NN) return;
    int beg = d_rowptr[g], end = d_rowptr[g + 1];
    const float4* pq = (const float4*)d_pq3;  // row = 32 float4
    float4 acc = make_float4(0.f, 0.f, 0.f, 0.f);
#pragma unroll 4
    for (int e = beg; e < end; e++) {
        int s = __ldg(&d_csrc[e]);
        float4 v = pq[(size_t)s * 32 + lane];
        acc.x += v.x; acc.y += v.y; acc.z += v.z; acc.w += v.w;
    }
    float inv = 1.f / fmaxf((float)(end - beg), 1.0f);
    float4 q = pq[(size_t)g * 32 + 16 + lane];
    float4 b = ((const float4*)bl)[lane];
    float4 o;
    o.x = acc.x * inv + b.x + q.x;
    o.y = acc.y * inv + b.y + q.y;
    o.z = acc.z * inv + b.z + q.z;
    o.w = acc.w * inv + b.w + q.w;
    ((float4*)d_h3)[(size_t)g * 16 + lane] = o;
}

// ---------------- SGEMM: C[M,N] = A[M,K] * B[N,K]^T (+bias, relu) ----------------
__global__ void __launch_bounds__(256, 2) k_sgemm(
    const float* __restrict__ A, const float* __restrict__ B,
    float* __restrict__ C, int M, int N, int K,
    const float* __restrict__ bias, int relu) {
    __shared__ float As[8][128];
    __shared__ float Bs[8][128];
    int tid = threadIdx.x;
    int bm = blockIdx.y * 128;
    int bn = blockIdx.x * 128;
    int tx = tid & 15, ty = tid >> 4;
    int lr = tid >> 1;
    int lc = (tid & 1) * 4;
    float acc[8][8];
#pragma unroll
    for (int i = 0; i < 8; i++)
#pragma unroll
        for (int j = 0; j < 8; j++) acc[i][j] = 0.f;

    const float* Aptr = A + (size_t)(bm + lr) * K + lc;
    const float* Bptr = B + (size_t)(bn + lr) * K + lc;
    bool aval = (bm + lr) < M;

    for (int k0 = 0; k0 < K; k0 += 8) {
        float4 av = aval ? *(const float4*)(Aptr + k0) : make_float4(0.f, 0.f, 0.f, 0.f);
        float4 bv = *(const float4*)(Bptr + k0);
        As[lc + 0][lr] = av.x; As[lc + 1][lr] = av.y;
        As[lc + 2][lr] = av.z; As[lc + 3][lr] = av.w;
        Bs[lc + 0][lr] = bv.x; Bs[lc + 1][lr] = bv.y;
        Bs[lc + 2][lr] = bv.z; Bs[lc + 3][lr] = bv.w;
        __syncthreads();
#pragma unroll
        for (int kk = 0; kk < 8; kk++) {
            float4 a0 = *(const float4*)&As[kk][ty * 8];
            float4 a1 = *(const float4*)&As[kk][ty * 8 + 4];
            float4 b0 = *(const float4*)&Bs[kk][tx * 8];
            float4 b1 = *(const float4*)&Bs[kk][tx * 8 + 4];
            float a[8] = {a0.x, a0.y, a0.z, a0.w, a1.x, a1.y, a1.z, a1.w};
            float b[8] = {b0.x, b0.y, b0.z, b0.w, b1.x, b1.y, b1.z, b1.w};
#pragma unroll
            for (int i = 0; i < 8; i++)
#pragma unroll
                for (int j = 0; j < 8; j++) acc[i][j] += a[i] * b[j];
        }
        __syncthreads();
    }
#pragma unroll
    for (int i = 0; i < 8; i++) {
        int row = bm + ty * 8 + i;
        if (row >= M) continue;
#pragma unroll
        for (int j = 0; j < 8; j += 4) {
            int col = bn + tx * 8 + j;
            float4 v = make_float4(acc[i][j], acc[i][j + 1], acc[i][j + 2], acc[i][j + 3]);
            if (bias) {
                v.x += bias[col]; v.y += bias[col + 1];
                v.z += bias[col + 2]; v.w += bias[col + 3];
            }
            if (relu) {
                v.x = fmaxf(v.x, 0.f); v.y = fmaxf(v.y, 0.f);
                v.z = fmaxf(v.z, 0.f); v.w = fmaxf(v.w, 0.f);
            }
            *(float4*)&C[(size_t)row * N + col] = v;
        }
    }
}

// ---------------- map encoder ----------------
__global__ void k_conv1(const float* __restrict__ in, const float* __restrict__ w,
                        const float* __restrict__ b) {
    int idx = blockIdx.x * blockDim.x + threadIdx.x;
    if (idx >= 256 * 1573) return;
    int oc = idx / 1573, p = idx % 1573;
    int od = p / 121, r = p % 121, oh = r / 11, ow = r % 11;
    const float* wp = w + oc * 75;
    float acc = 0.f;
#pragma unroll
    for (int kd = 0; kd < 3; kd++)
#pragma unroll
        for (int kh = 0; kh < 5; kh++)
#pragma unroll
            for (int kw = 0; kw < 5; kw++)
                acc += in[(od + kd) * 225 + (oh + kh) * 15 + (ow + kw)] *
                       wp[kd * 25 + kh * 5 + kw];
    d_m1[idx] = fmaxf(acc + b[oc], 0.f);
}

__global__ void k_conv2(const float* __restrict__ w, const float* __restrict__ b) {
    __shared__ __align__(16) float slab[13 * 132];
    __shared__ float ws[32];
    int oc = blockIdx.x;
    int tid = threadIdx.x;
    int od = tid / 9, oh = tid % 9;
    bool act = tid < 99;
    float acc[9];
#pragma unroll
    for (int i = 0; i < 9; i++) acc[i] = 0.f;

    for (int ic = 0; ic < 256; ic++) {
        __syncthreads();
        const float* src = d_m1 + ic * 1573;
        for (int i = tid; i < 1573; i += 128) {
            int dd = i / 121, r = i % 121, hh = r / 11, ww = r % 11;
            slab[dd * 132 + hh * 12 + ww] = src[i];
        }
        if (tid < 27) ws[tid] = w[((size_t)oc * 256 + ic) * 27 + tid];
        __syncthreads();
        if (act) {
            float wr[27];
#pragma unroll
            for (int t = 0; t < 27; t++) wr[t] = ws[t];
#pragma unroll
            for (int kd = 0; kd < 3; kd++) {
#pragma unroll
                for (int kh = 0; kh < 3; kh++) {
                    const float* row = &slab[(od + kd) * 132 + (oh + kh) * 12];
                    float4 r0 = *(const float4*)(row);
                    float4 r1 = *(const float4*)(row + 4);
                    float4 r2 = *(const float4*)(row + 8);
                    float rv[12] = {r0.x, r0.y, r0.z, r0.w, r1.x, r1.y, r1.z, r1.w,
                                    r2.x, r2.y, r2.z, r2.w};
#pragma unroll
                    for (int kw = 0; kw < 3; kw++) {
                        float wv = wr[kd * 9 + kh * 3 + kw];
#pragma unroll
                        for (int ow = 0; ow < 9; ow++) acc[ow] += rv[ow + kw] * wv;
                    }
                }
            }
        }
    }
    if (act) {
        float bb = b[oc];
#pragma unroll
        for (int ow = 0; ow < 9; ow++)
            d_m2[(size_t)oc * 891 + od * 81 + oh * 9 + ow] = fmaxf(acc[ow] + bb, 0.f);
    }
}

// split-K Wm GEMV: grid (64, 8), atomic finish into zeroed d_mvec
__global__ void k_wm(const float* __restrict__ Wm) {
    __shared__ float red[256];
    int o = blockIdx.x;
    int chunk = blockIdx.y;
    const int CH = 114048 / 8;  // 14256
    int base = chunk * CH;
    const float* wr = Wm + (size_t)o * 114048 + base;
    const float* mv = d_m2 + base;
    float s = 0.f;
    for (int i = threadIdx.x * 4; i < CH; i += 256 * 4) {
        float4 a = *(const float4*)(wr + i);
        float4 v = *(const float4*)(mv + i);
        s += a.x * v.x + a.y * v.y + a.z * v.z + a.w * v.w;
    }
    red[threadIdx.x] = s;
    __syncthreads();
    for (int st = 128; st > 0; st >>= 1) {
        if (threadIdx.x < st) red[threadIdx.x] += red[threadIdx.x + st];
        __syncthreads();
    }
    if (threadIdx.x == 0) atomicAdd(&d_mvec[o], red[0]);
}

__global__ void k_mnorm(const float* __restrict__ bm) {
    __shared__ float smn[64], smx[64];
    int t = threadIdx.x;
    float v = d_mvec[t] + bm[t];
    smn[t] = v; smx[t] = v;
    __syncthreads();
    for (int st = 32; st > 0; st >>= 1) {
        if (t < st) {
            smn[t] = fminf(smn[t], smn[t + st]);
            smx[t] = fmaxf(smx[t], smx[t + st]);
        }
        __syncthreads();
    }
    float mn = smn[0], mx = smx[0];
    d_mnorm[t] = 0.65f * (v - mn) / (mx - mn);
}

// ---------------- h3 min/max ----------------
__global__ void k_hred1() {
    __shared__ float smn[256], smx[256];
    int tid = threadIdx.x;
    float mn = 3.4e38f, mx = -3.4e38f;
    for (size_t i = (size_t)blockIdx.x * 256 + tid; i < (size_t)NN * 64; i += (size_t)1024 * 256) {
        float v = d_h3[i];
        mn = fminf(mn, v); mx = fmaxf(mx, v);
    }
    smn[tid] = mn; smx[tid] = mx;
    __syncthreads();
    for (int st = 128; st > 0; st >>= 1) {
        if (tid < st) {
            smn[tid] = fminf(smn[tid], smn[tid + st]);
            smx[tid] = fmaxf(smx[tid], smx[tid + st]);
        }
        __syncthreads();
    }
    if (tid == 0) { d_pmin[blockIdx.x] = smn[0]; d_pmax[blockIdx.x] = smx[0]; }
}
__global__ void k_hred2() {
    __shared__ float smn[1024], smx[1024];
    int t = threadIdx.x;
    smn[t] = d_pmin[t]; smx[t] = d_pmax[t];
    __syncthreads();
    for (int st = 512; st > 0; st >>= 1) {
        if (t < st) {
            smn[t] = fminf(smn[t], smn[t + st]);
            smx[t] = fmaxf(smx[t], smx[t + st]);
        }
        __syncthreads();
    }
    if (t == 0) {
        float mn = smn[0], mx = smx[0];
        float a = 0.35f / (mx - mn);
        d_hstats[0] = a;
        d_hstats[1] = -mn * a;
    }
}

__global__ void k_xn() {
    int i4 = blockIdx.x * blockDim.x + threadIdx.x;
    if (i4 >= NN * 16) return;
    float a = d_hstats[0], c = d_hstats[1];
    int f4 = i4 & 15;
    float4 h = *(const float4*)&d_h3[(size_t)i4 * 4];
    float4 mn = *(const float4*)&d_mnorm[f4 * 4];
    float4 o;
    o.x = a * h.x + c + mn.x;
    o.y = a * h.y + c + mn.y;
    o.z = a * h.z + c + mn.z;
    o.w = a * h.w + c + mn.w;
    *(float4*)&d_xn[(size_t)i4 * 4] = o;
}

// ---------------- final layer + softmax ----------------
__global__ void k_head(const float* __restrict__ W2, const float* __restrict__ b2,
                       float* __restrict__ out) {
    __shared__ float w2s[3][64];
    __shared__ float b2s[3];
    int tid = threadIdx.x;
    if (tid < 192) w2s[tid / 64][tid % 64] = W2[tid];
    if (tid < 3) b2s[tid] = b2[tid];
    __syncthreads();
    int i = blockIdx.x * blockDim.x + tid;
    if (i >= NN) return;
    const float* y = d_y1 + (size_t)i * 128;
    float s0 = b2s[0], s1 = b2s[1], s2 = b2s[2];
#pragma unroll
    for (int f = 0; f < 64; f += 4) {
        float4 v = *(const float4*)(y + f);
        s0 += v.x * w2s[0][f] + v.y * w2s[0][f + 1] + v.z * w2s[0][f + 2] + v.w * w2s[0][f + 3];
        s1 += v.x * w2s[1][f] + v.y * w2s[1][f + 1] + v.z * w2s[1][f + 2] + v.w * w2s[1][f + 3];
        s2 += v.x * w2s[2][f] + v.y * w2s[2][f + 1] + v.z * w2s[2][f + 2] + v.w * w2s[2][f + 3];
    }
    float m = fmaxf(s0, fmaxf(s1, s2));
    float e0 = expf(s0 - m), e1 = expf(s1 - m), e2 = expf(s2 - m);
    float inv = 1.f / (e0 + e1 + e2);
    out[(size_t)i * 3 + 0] = e0 * inv;
    out[(size_t)i * 3 + 1] = e1 * inv;
    out[(size_t)i * 3 + 2] = e2 * inv;
}

// ---------------- launch ----------------
extern "C" void kernel_launch(void* const* d_in, const int* in_sizes, int n_in,
                              void* d_out, int out_size) {
    (void)in_sizes; (void)n_in; (void)out_size;
    const float* node = (const float*)d_in[0];
    const int* ei = (const int*)d_in[1];
    const float* mapd = (const float*)d_in[2];
    const float* Wl1 = (const float*)d_in[3];
    const float* bl1 = (const float*)d_in[4];
    const float* Wr1 = (const float*)d_in[5];
    const float* Wl2 = (const float*)d_in[6];
    const float* bl2 = (const float*)d_in[7];
    const float* Wr2 = (const float*)d_in[8];
    const float* Wl3 = (const float*)d_in[9];
    const float* bl3 = (const float*)d_in[10];
    const float* Wr3 = (const float*)d_in[11];
    const float* k1 = (const float*)d_in[12];
    const float* cb1 = (const float*)d_in[13];
    const float* k2 = (const float*)d_in[14];
    const float* cb2 = (const float*)d_in[15];
    const float* Wm = (const float*)d_in[16];
    const float* bm = (const float*)d_in[17];
    const float* W1 = (const float*)d_in[18];
    const float* b1 = (const float*)d_in[19];
    const float* W2 = (const float*)d_in[20];
    const float* b2 = (const float*)d_in[21];
    float* out = (float*)d_out;

    void *p_cnt, *p_mvec;
    void *p_mx, *p_wc1, *p_h1, *p_wc2, *p_pq2, *p_h2, *p_wc3, *p_pq3;
    void *p_xn, *p_w1p, *p_b1p, *p_y1;
    cudaGetSymbolAddress(&p_cnt, d_cnt);
    cudaGetSymbolAddress(&p_mvec, d_mvec);
    cudaGetSymbolAddress(&p_mx, d_mx);
    cudaGetSymbolAddress(&p_wc1, d_wc1);
    cudaGetSymbolAddress(&p_h1, d_h1);
    cudaGetSymbolAddress(&p_wc2, d_wc2);
    cudaGetSymbolAddress(&p_pq2, d_pq2);
    cudaGetSymbolAddress(&p_h2, d_h2);
    cudaGetSymbolAddress(&p_wc3, d_wc3);
    cudaGetSymbolAddress(&p_pq3, d_pq3);
    cudaGetSymbolAddress(&p_xn, d_xn);
    cudaGetSymbolAddress(&p_w1p, d_w1p);
    cudaGetSymbolAddress(&p_b1p, d_b1p);
    cudaGetSymbolAddress(&p_y1, d_y1);

    cudaMemsetAsync(p_cnt, 0, NN * sizeof(int));
    cudaMemsetAsync(p_mvec, 0, 64 * sizeof(float));

    // weight packs
    k_pack1<<<48, 256>>>(Wl1, Wr1);
    k_pack2<<<256, 256>>>(Wl2, Wr2);
    k_pack3<<<64, 256>>>(Wl3, Wr3);
    k_packW1<<<32, 256>>>(W1, b1);

    // CSR build
    k_degcnt<<<(NE + 255) / 256, 256>>>(ei);
    k_scan1<<<NB1, 256>>>();
    k_scan2<<<1, 256>>>();
    k_scan3<<<NB1, 256>>>();
    k_scatter<<<(NE + 255) / 256, 256>>>(ei);

    // layer 1
    k_aggA<<<(NN * 32 + 255) / 256, 256>>>(node);
    k_sgemm<<<dim3(2, 391), 256>>>((const float*)p_mx, (const float*)p_wc1,
                                   (float*)p_h1, NN, 256, 48, bl1, 1);
    // layer 2 (project-first)
    k_sgemm<<<dim3(2, 391), 256>>>((const float*)p_h1, (const float*)p_wc2,
                                   (float*)p_pq2, NN, 256, 256, (const float*)nullptr, 0);
    k_aggB<<<(NN * 32 + 255) / 256, 256>>>(bl2);
    // layer 3
    k_sgemm<<<dim3(1, 391), 256>>>((const float*)p_h2, (const float*)p_wc3,
                                   (float*)p_pq3, NN, 128, 128, (const float*)nullptr, 0);
    k_aggC<<<(NN * 16 + 255) / 256, 256>>>(bl3);

    // map encoder
    k_conv1<<<(256 * 1573 + 255) / 256, 256>>>(mapd, k1, cb1);
    k_conv2<<<128, 128>>>(k2, cb2);
    k_wm<<<dim3(64, 8), 256>>>(Wm);
    k_mnorm<<<1, 64>>>(bm);

    // normalize + combine + head
    k_hred1<<<1024, 256>>>();
    k_hred2<<<1, 1024>>>();
    k_xn<<<(NN * 16 + 255) / 256, 256>>>();
    k_sgemm<<<dim3(1, 391), 256>>>((const float*)p_xn, (const float*)p_w1p,
                                   (float*)p_y1, NN, 128, 64, (const float*)p_b1p, 1);
    k_head<<<(NN + 255) / 256, 256>>>(W2, b2, out);
}

// round 3
// speedup vs baseline: 1.6382x; 1.1565x over previous
#include <cuda_runtime.h>
#include <mma.h>
#include <math.h>

using namespace nvcuda;

#define NN 50000
#define MP 50048   // padded rows: 391 * 128
#define NE 800000
#define NB1 196    // ceil(NN/256)

// ---------------- scratch ----------------
static __device__ int   d_cnt[NN];
static __device__ int   d_rowptr[NN + 1];
static __device__ int   d_cursor[NN];
static __device__ int   d_csrc[NE];
static __device__ int   d_part[256];
static __device__ float d_mx[(size_t)MP * 48];
static __device__ float d_wc1[256 * 48];
static __device__ float d_h1[(size_t)MP * 256];
static __device__ float d_wc2[256 * 256];
static __device__ float d_pq2[(size_t)MP * 256];  // [p(128)|q(128)]
static __device__ float d_h2[(size_t)MP * 128];
static __device__ float d_wc3[128 * 128];
static __device__ float d_pq3[(size_t)MP * 128];  // [p(64)|q(64)]
static __device__ float d_h3[(size_t)MP * 64];
static __device__ float d_xn[(size_t)MP * 64];
static __device__ float d_w1p[128 * 64];
static __device__ float d_y1[(size_t)MP * 128];
static __device__ float d_m1[256 * 13 * 11 * 11];
static __device__ float d_m2[128 * 11 * 9 * 9];
static __device__ float d_mvec[64];
static __device__ float d_mnorm[64];
static __device__ float d_pmin[1024];
static __device__ float d_pmax[1024];
static __device__ float d_hstats[4];

// ---------------- weight packing ----------------
__global__ void k_pack1(const float* __restrict__ Wl, const float* __restrict__ Wr) {
    int i = blockIdx.x * blockDim.x + threadIdx.x;
    if (i >= 256 * 48) return;
    int n = i / 48, f = i % 48;
    float v = 0.f;
    if (f < 21) v = Wl[n * 21 + f];
    else if (f < 42) v = Wr[n * 21 + (f - 21)];
    d_wc1[i] = v;
}
__global__ void k_pack2(const float* __restrict__ Wl, const float* __restrict__ Wr) {
    int i = blockIdx.x * blockDim.x + threadIdx.x;
    if (i >= 256 * 256) return;
    int n = i / 256, f = i % 256;
    d_wc2[i] = (n < 128) ? Wl[n * 256 + f] : Wr[(n - 128) * 256 + f];
}
__global__ void k_pack3(const float* __restrict__ Wl, const float* __restrict__ Wr) {
    int i = blockIdx.x * blockDim.x + threadIdx.x;
    if (i >= 128 * 128) return;
    int n = i / 128, f = i % 128;
    d_wc3[i] = (n < 64) ? Wl[n * 128 + f] : Wr[(n - 64) * 128 + f];
}
__global__ void k_packW1(const float* __restrict__ W1) {
    int i = blockIdx.x * blockDim.x + threadIdx.x;
    if (i >= 128 * 64) return;
    int n = i / 64;
    d_w1p[i] = (n < 64) ? W1[i] : 0.f;
}

// ---------------- CSR build ----------------
__global__ void k_degcnt(const int* __restrict__ ei) {
    int e = blockIdx.x * blockDim.x + threadIdx.x;
    if (e < NE) atomicAdd(&d_cnt[ei[NE + e]], 1);
}
__global__ void k_scan1() {
    __shared__ int sh[256];
    int t = threadIdx.x;
    int i = blockIdx.x * 256 + t;
    int v = (i < NN) ? d_cnt[i] : 0;
    sh[t] = v;
    __syncthreads();
#pragma unroll
    for (int off = 1; off < 256; off <<= 1) {
        int a = (t >= off) ? sh[t - off] : 0;
        __syncthreads();
        sh[t] += a;
        __syncthreads();
    }
    if (i < NN) d_rowptr[i] = sh[t] - v;
    if (t == 255) d_part[blockIdx.x] = sh[255];
}
__global__ void k_scan2() {
    __shared__ int sh[256];
    int t = threadIdx.x;
    int v = (t < NB1) ? d_part[t] : 0;
    sh[t] = v;
    __syncthreads();
#pragma unroll
    for (int off = 1; off < 256; off <<= 1) {
        int a = (t >= off) ? sh[t - off] : 0;
        __syncthreads();
        sh[t] += a;
        __syncthreads();
    }
    if (t < NB1) d_part[t] = sh[t] - v;
}
__global__ void k_scan3() {
    int i = blockIdx.x * 256 + threadIdx.x;
    if (i < NN) {
        int r = d_rowptr[i] + d_part[blockIdx.x];
        d_rowptr[i] = r;
        d_cursor[i] = r;
    }
    if (i == 0) d_rowptr[NN] = NE;
}
__global__ void k_scatter(const int* __restrict__ ei) {
    int e = blockIdx.x * blockDim.x + threadIdx.x;
    if (e >= NE) return;
    int s = ei[e], d = ei[NE + e];
    int pos = atomicAdd(&d_cursor[d], 1);
    d_csrc[pos] = s;
}

// ---------------- CSR aggregation ----------------
__global__ void k_aggA(const float* __restrict__ x) {
    int w = (blockIdx.x * blockDim.x + threadIdx.x) >> 5;
    int lane = threadIdx.x & 31;
    if (w >= NN) return;
    int beg = d_rowptr[w], end = d_rowptr[w + 1];
    float acc = 0.f;
    for (int e0 = beg; e0 < end; e0 += 32) {
        int cnt = min(32, end - e0);
        int idx = (e0 + lane < end) ? d_csrc[e0 + lane] : 0;
        for (int j = 0; j < cnt; j++) {
            int s = __shfl_sync(0xffffffffu, idx, j);
            if (lane < 21) acc += x[(size_t)s * 21 + lane];
        }
    }
    float inv = 1.f / fmaxf((float)(end - beg), 1.0f);
    if (lane < 21) {
        d_mx[(size_t)w * 48 + lane] = acc * inv;
        d_mx[(size_t)w * 48 + 21 + lane] = x[(size_t)w * 21 + lane];
    } else if (lane < 27) {
        d_mx[(size_t)w * 48 + 21 + lane] = 0.f;
    }
}
__global__ void k_aggB(const float* __restrict__ bl) {
    int w = (blockIdx.x * blockDim.x + threadIdx.x) >> 5;
    int lane = threadIdx.x & 31;
    if (w >= NN) return;
    int beg = d_rowptr[w], end = d_rowptr[w + 1];
    const float4* pq = (const float4*)d_pq2;
    float4 acc = make_float4(0.f, 0.f, 0.f, 0.f);
#pragma unroll 4
    for (int e = beg; e < end; e++) {
        int s = __ldg(&d_csrc[e]);
        float4 v = pq[(size_t)s * 64 + lane];
        acc.x += v.x; acc.y += v.y; acc.z += v.z; acc.w += v.w;
    }
    float inv = 1.f / fmaxf((float)(end - beg), 1.0f);
    float4 q = pq[(size_t)w * 64 + 32 + lane];
    float4 b = ((const float4*)bl)[lane];
    float4 o;
    o.x = fmaxf(acc.x * inv + b.x + q.x, 0.f);
    o.y = fmaxf(acc.y * inv + b.y + q.y, 0.f);
    o.z = fmaxf(acc.z * inv + b.z + q.z, 0.f);
    o.w = fmaxf(acc.w * inv + b.w + q.w, 0.f);
    ((float4*)d_h2)[(size_t)w * 32 + lane] = o;
}
__global__ void k_aggC(const float* __restrict__ bl) {
    int g = (blockIdx.x * blockDim.x + threadIdx.x) >> 4;
    int lane = threadIdx.x & 15;
    if (g >= NN) return;
    int beg = d_rowptr[g], end = d_rowptr[g + 1];
    const float4* pq = (const float4*)d_pq3;
    float4 acc = make_float4(0.f, 0.f, 0.f, 0.f);
#pragma unroll 4
    for (int e = beg; e < end; e++) {
        int s = __ldg(&d_csrc[e]);
        float4 v = pq[(size_t)s * 32 + lane];
        acc.x += v.x; acc.y += v.y; acc.z += v.z; acc.w += v.w;
    }
    float inv = 1.f / fmaxf((float)(end - beg), 1.0f);
    float4 q = pq[(size_t)g * 32 + 16 + lane];
    float4 b = ((const float4*)bl)[lane];
    float4 o;
    o.x = acc.x * inv + b.x + q.x;
    o.y = acc.y * inv + b.y + q.y;
    o.z = acc.z * inv + b.z + q.z;
    o.w = acc.w * inv + b.w + q.w;
    ((float4*)d_h3)[(size_t)g * 16 + lane] = o;
}

// ---------------- tf32 tensor-core GEMM ----------------
// C[MP, N] = A[MP, K] @ B[N, K]^T.  N in {128, 256}, K multiple of 16.
// Optional A-side prolog: a <- max(a + abias[k], 0)   (fuses previous layer's bias+relu)
// Grid: (N/128, 391). 8 warps: 2 (M) x 4 (N); warp tile 64x32.
__global__ void __launch_bounds__(256) k_tgemm(
    const float* __restrict__ A, const float* __restrict__ B, float* __restrict__ C,
    int N, int K, const float* __restrict__ abias) {
    __shared__ float As[128][20];
    __shared__ float Bs[128][20];
    int tid = threadIdx.x;
    int wid = tid >> 5;
    int bm = blockIdx.y * 128;
    int bn = blockIdx.x * 128;
    int wm = (wid >> 2) * 64;
    int wn = (wid & 3) * 32;
    int lrow = tid >> 1;
    int lcol = (tid & 1) * 8;

    wmma::fragment<wmma::accumulator, 16, 16, 8, float> cf[4][2];
#pragma unroll
    for (int i = 0; i < 4; i++)
#pragma unroll
        for (int j = 0; j < 2; j++) wmma::fill_fragment(cf[i][j], 0.f);

    const float* Arow = A + (size_t)(bm + lrow) * K + lcol;
    const float* Brow = B + (size_t)(bn + lrow) * K + lcol;

    for (int k0 = 0; k0 < K; k0 += 16) {
        float4 a0 = *(const float4*)(Arow + k0);
        float4 a1 = *(const float4*)(Arow + k0 + 4);
        if (abias) {
            const float* bp = abias + k0 + lcol;
            a0.x = fmaxf(a0.x + bp[0], 0.f); a0.y = fmaxf(a0.y + bp[1], 0.f);
            a0.z = fmaxf(a0.z + bp[2], 0.f); a0.w = fmaxf(a0.w + bp[3], 0.f);
            a1.x = fmaxf(a1.x + bp[4], 0.f); a1.y = fmaxf(a1.y + bp[5], 0.f);
            a1.z = fmaxf(a1.z + bp[6], 0.f); a1.w = fmaxf(a1.w + bp[7], 0.f);
        }
        float4 b0 = *(const float4*)(Brow + k0);
        float4 b1 = *(const float4*)(Brow + k0 + 4);
        *(float4*)&As[lrow][lcol] = a0;
        *(float4*)&As[lrow][lcol + 4] = a1;
        *(float4*)&Bs[lrow][lcol] = b0;
        *(float4*)&Bs[lrow][lcol + 4] = b1;
        __syncthreads();
#pragma unroll
        for (int ks = 0; ks < 16; ks += 8) {
            wmma::fragment<wmma::matrix_a, 16, 16, 8, wmma::precision::tf32, wmma::row_major> af[4];
            wmma::fragment<wmma::matrix_b, 16, 16, 8, wmma::precision::tf32, wmma::col_major> bf[2];
#pragma unroll
            for (int i = 0; i < 4; i++) {
                wmma::load_matrix_sync(af[i], &As[wm + i * 16][ks], 20);
#pragma unroll
                for (int t = 0; t < af[i].num_elements; t++)
                    af[i].x[t] = wmma::__float_to_tf32(af[i].x[t]);
            }
#pragma unroll
            for (int j = 0; j < 2; j++) {
                wmma::load_matrix_sync(bf[j], &Bs[wn + j * 16][ks], 20);
#pragma unroll
                for (int t = 0; t < bf[j].num_elements; t++)
                    bf[j].x[t] = wmma::__float_to_tf32(bf[j].x[t]);
            }
#pragma unroll
            for (int i = 0; i < 4; i++)
#pragma unroll
                for (int j = 0; j < 2; j++)
                    wmma::mma_sync(cf[i][j], af[i], bf[j], cf[i][j]);
        }
        __syncthreads();
    }
#pragma unroll
    for (int i = 0; i < 4; i++)
#pragma unroll
        for (int j = 0; j < 2; j++)
            wmma::store_matrix_sync(&C[(size_t)(bm + wm + i * 16) * N + bn + wn + j * 16],
                                    cf[i][j], N, wmma::mem_row_major);
}

// ---------------- map encoder ----------------
__global__ void k_conv1(const float* __restrict__ in, const float* __restrict__ w,
                        const float* __restrict__ b) {
    int idx = blockIdx.x * blockDim.x + threadIdx.x;
    if (idx >= 256 * 1573) return;
    int oc = idx / 1573, p = idx % 1573;
    int od = p / 121, r = p % 121, oh = r / 11, ow = r % 11;
    const float* wp = w + oc * 75;
    float acc = 0.f;
#pragma unroll
    for (int kd = 0; kd < 3; kd++)
#pragma unroll
        for (int kh = 0; kh < 5; kh++)
#pragma unroll
            for (int kw = 0; kw < 5; kw++)
                acc += in[(od + kd) * 225 + (oh + kh) * 15 + (ow + kw)] *
                       wp[kd * 25 + kh * 5 + kw];
    d_m1[idx] = fmaxf(acc + b[oc], 0.f);
}

__global__ void k_conv2(const float* __restrict__ w, const float* __restrict__ b) {
    __shared__ __align__(16) float slab[13 * 132];
    __shared__ float ws[32];
    int oc = blockIdx.x;
    int tid = threadIdx.x;
    int od = tid / 9, oh = tid % 9;
    bool act = tid < 99;
    float acc[9];
#pragma unroll
    for (int i = 0; i < 9; i++) acc[i] = 0.f;

    for (int ic = 0; ic < 256; ic++) {
        __syncthreads();
        const float* src = d_m1 + ic * 1573;
        for (int i = tid; i < 1573; i += 128) {
            int dd = i / 121, r = i % 121, hh = r / 11, ww = r % 11;
            slab[dd * 132 + hh * 12 + ww] = src[i];
        }
        if (tid < 27) ws[tid] = w[((size_t)oc * 256 + ic) * 27 + tid];
        __syncthreads();
        if (act) {
            float wr[27];
#pragma unroll
            for (int t = 0; t < 27; t++) wr[t] = ws[t];
#pragma unroll
            for (int kd = 0; kd < 3; kd++) {
#pragma unroll
                for (int kh = 0; kh < 3; kh++) {
                    const float* row = &slab[(od + kd) * 132 + (oh + kh) * 12];
                    float4 r0 = *(const float4*)(row);
                    float4 r1 = *(const float4*)(row + 4);
                    float4 r2 = *(const float4*)(row + 8);
                    float rv[12] = {r0.x, r0.y, r0.z, r0.w, r1.x, r1.y, r1.z, r1.w,
                                    r2.x, r2.y, r2.z, r2.w};
#pragma unroll
                    for (int kw = 0; kw < 3; kw++) {
                        float wv = wr[kd * 9 + kh * 3 + kw];
#pragma unroll
                        for (int ow = 0; ow < 9; ow++) acc[ow] += rv[ow + kw] * wv;
                    }
                }
            }
        }
    }
    if (act) {
        float bb = b[oc];
#pragma unroll
        for (int ow = 0; ow < 9; ow++)
            d_m2[(size_t)oc * 891 + od * 81 + oh * 9 + ow] = fmaxf(acc[ow] + bb, 0.f);
    }
}

__global__ void k_wm(const float* __restrict__ Wm) {
    __shared__ float red[256];
    int o = blockIdx.x;
    int chunk = blockIdx.y;
    const int CH = 114048 / 8;
    int base = chunk * CH;
    const float* wr = Wm + (size_t)o * 114048 + base;
    const float* mv = d_m2 + base;
    float s = 0.f;
    for (int i = threadIdx.x * 4; i < CH; i += 256 * 4) {
        float4 a = *(const float4*)(wr + i);
        float4 v = *(const float4*)(mv + i);
        s += a.x * v.x + a.y * v.y + a.z * v.z + a.w * v.w;
    }
    red[threadIdx.x] = s;
    __syncthreads();
    for (int st = 128; st > 0; st >>= 1) {
        if (threadIdx.x < st) red[threadIdx.x] += red[threadIdx.x + st];
        __syncthreads();
    }
    if (threadIdx.x == 0) atomicAdd(&d_mvec[o], red[0]);
}

__global__ void k_mnorm(const float* __restrict__ bm) {
    __shared__ float smn[64], smx[64];
    int t = threadIdx.x;
    float v = d_mvec[t] + bm[t];
    smn[t] = v; smx[t] = v;
    __syncthreads();
    for (int st = 32; st > 0; st >>= 1) {
        if (t < st) {
            smn[t] = fminf(smn[t], smn[t + st]);
            smx[t] = fmaxf(smx[t], smx[t + st]);
        }
        __syncthreads();
    }
    float mn = smn[0], mx = smx[0];
    d_mnorm[t] = 0.65f * (v - mn) / (mx - mn);
}

// ---------------- h3 min/max ----------------
__global__ void k_hred1() {
    __shared__ float smn[256], smx[256];
    int tid = threadIdx.x;
    float mn = 3.4e38f, mx = -3.4e38f;
    for (size_t i = (size_t)blockIdx.x * 256 + tid; i < (size_t)NN * 64; i += (size_t)1024 * 256) {
        float v = d_h3[i];
        mn = fminf(mn, v); mx = fmaxf(mx, v);
    }
    smn[tid] = mn; smx[tid] = mx;
    __syncthreads();
    for (int st = 128; st > 0; st >>= 1) {
        if (tid < st) {
            smn[tid] = fminf(smn[tid], smn[tid + st]);
            smx[tid] = fmaxf(smx[tid], smx[tid + st]);
        }
        __syncthreads();
    }
    if (tid == 0) { d_pmin[blockIdx.x] = smn[0]; d_pmax[blockIdx.x] = smx[0]; }
}
__global__ void k_hred2() {
    __shared__ float smn[1024], smx[1024];
    int t = threadIdx.x;
    smn[t] = d_pmin[t]; smx[t] = d_pmax[t];
    __syncthreads();
    for (int st = 512; st > 0; st >>= 1) {
        if (t < st) {
            smn[t] = fminf(smn[t], smn[t + st]);
            smx[t] = fmaxf(smx[t], smx[t + st]);
        }
        __syncthreads();
    }
    if (t == 0) {
        float mn = smn[0], mx = smx[0];
        float a = 0.35f / (mx - mn);
        d_hstats[0] = a;
        d_hstats[1] = -mn * a;
    }
}

__global__ void k_xn() {
    int i4 = blockIdx.x * blockDim.x + threadIdx.x;
    if (i4 >= NN * 16) return;
    float a = d_hstats[0], c = d_hstats[1];
    int f4 = i4 & 15;
    float4 h = *(const float4*)&d_h3[(size_t)i4 * 4];
    float4 mn = *(const float4*)&d_mnorm[f4 * 4];
    float4 o;
    o.x = a * h.x + c + mn.x;
    o.y = a * h.y + c + mn.y;
    o.z = a * h.z + c + mn.z;
    o.w = a * h.w + c + mn.w;
    *(float4*)&d_xn[(size_t)i4 * 4] = o;
}

// ---------------- final layer + softmax (applies b1 + relu to raw y1) ----------------
__global__ void k_head(const float* __restrict__ W2, const float* __restrict__ b2,
                       const float* __restrict__ b1, float* __restrict__ out) {
    __shared__ float w2s[3][64];
    __shared__ float b2s[3];
    __shared__ float b1s[64];
    int tid = threadIdx.x;
    if (tid < 192) w2s[tid / 64][tid % 64] = W2[tid];
    if (tid < 3) b2s[tid] = b2[tid];
    if (tid >= 192 && tid < 256) b1s[tid - 192] = b1[tid - 192];
    __syncthreads();
    int i = blockIdx.x * blockDim.x + tid;
    if (i >= NN) return;
    const float* y = d_y1 + (size_t)i * 128;
    float s0 = b2s[0], s1 = b2s[1], s2 = b2s[2];
#pragma unroll
    for (int f = 0; f < 64; f += 4) {
        float4 v = *(const float4*)(y + f);
        v.x = fmaxf(v.x + b1s[f], 0.f);
        v.y = fmaxf(v.y + b1s[f + 1], 0.f);
        v.z = fmaxf(v.z + b1s[f + 2], 0.f);
        v.w = fmaxf(v.w + b1s[f + 3], 0.f);
        s0 += v.x * w2s[0][f] + v.y * w2s[0][f + 1] + v.z * w2s[0][f + 2] + v.w * w2s[0][f + 3];
        s1 += v.x * w2s[1][f] + v.y * w2s[1][f + 1] + v.z * w2s[1][f + 2] + v.w * w2s[1][f + 3];
        s2 += v.x * w2s[2][f] + v.y * w2s[2][f + 1] + v.z * w2s[2][f + 2] + v.w * w2s[2][f + 3];
    }
    float m = fmaxf(s0, fmaxf(s1, s2));
    float e0 = expf(s0 - m), e1 = expf(s1 - m), e2 = expf(s2 - m);
    float inv = 1.f / (e0 + e1 + e2);
    out[(size_t)i * 3 + 0] = e0 * inv;
    out[(size_t)i * 3 + 1] = e1 * inv;
    out[(size_t)i * 3 + 2] = e2 * inv;
}

// ---------------- launch ----------------
extern "C" void kernel_launch(void* const* d_in, const int* in_sizes, int n_in,
                              void* d_out, int out_size) {
    (void)in_sizes; (void)n_in; (void)out_size;
    const float* node = (const float*)d_in[0];
    const int* ei = (const int*)d_in[1];
    const float* mapd = (const float*)d_in[2];
    const float* Wl1 = (const float*)d_in[3];
    const float* bl1 = (const float*)d_in[4];
    const float* Wr1 = (const float*)d_in[5];
    const float* Wl2 = (const float*)d_in[6];
    const float* bl2 = (const float*)d_in[7];
    const float* Wr2 = (const float*)d_in[8];
    const float* Wl3 = (const float*)d_in[9];
    const float* bl3 = (const float*)d_in[10];
    const float* Wr3 = (const float*)d_in[11];
    const float* k1 = (const float*)d_in[12];
    const float* cb1 = (const float*)d_in[13];
    const float* k2 = (const float*)d_in[14];
    const float* cb2 = (const float*)d_in[15];
    const float* Wm = (const float*)d_in[16];
    const float* bm = (const float*)d_in[17];
    const float* W1 = (const float*)d_in[18];
    const float* b1 = (const float*)d_in[19];
    const float* W2 = (const float*)d_in[20];
    const float* b2 = (const float*)d_in[21];
    float* out = (float*)d_out;

    void *p_cnt, *p_mvec;
    void *p_mx, *p_wc1, *p_h1, *p_wc2, *p_pq2, *p_h2, *p_wc3, *p_pq3;
    void *p_xn, *p_w1p, *p_y1;
    cudaGetSymbolAddress(&p_cnt, d_cnt);
    cudaGetSymbolAddress(&p_mvec, d_mvec);
    cudaGetSymbolAddress(&p_mx, d_mx);
    cudaGetSymbolAddress(&p_wc1, d_wc1);
    cudaGetSymbolAddress(&p_h1, d_h1);
    cudaGetSymbolAddress(&p_wc2, d_wc2);
    cudaGetSymbolAddress(&p_pq2, d_pq2);
    cudaGetSymbolAddress(&p_h2, d_h2);
    cudaGetSymbolAddress(&p_wc3, d_wc3);
    cudaGetSymbolAddress(&p_pq3, d_pq3);
    cudaGetSymbolAddress(&p_xn, d_xn);
    cudaGetSymbolAddress(&p_w1p, d_w1p);
    cudaGetSymbolAddress(&p_y1, d_y1);

    cudaMemsetAsync(p_cnt, 0, NN * sizeof(int));
    cudaMemsetAsync(p_mvec, 0, 64 * sizeof(float));

    // weight packs
    k_pack1<<<48, 256>>>(Wl1, Wr1);
    k_pack2<<<256, 256>>>(Wl2, Wr2);
    k_pack3<<<64, 256>>>(Wl3, Wr3);
    k_packW1<<<32, 256>>>(W1);

    // CSR build
    k_degcnt<<<(NE + 255) / 256, 256>>>(ei);
    k_scan1<<<NB1, 256>>>();
    k_scan2<<<1, 256>>>();
    k_scan3<<<NB1, 256>>>();
    k_scatter<<<(NE + 255) / 256, 256>>>(ei);

    // layer 1: h1raw = [mean|x] @ wc1^T   (bias+relu deferred into gemm2 A-load)
    k_aggA<<<(NN * 32 + 255) / 256, 256>>>(node);
    k_tgemm<<<dim3(2, 391), 256>>>((const float*)p_mx, (const float*)p_wc1,
                                   (float*)p_h1, 256, 48, (const float*)nullptr);
    // layer 2: pq2 = relu(h1raw + bl1) @ wc2^T  (project-first)
    k_tgemm<<<dim3(2, 391), 256>>>((const float*)p_h1, (const float*)p_wc2,
                                   (float*)p_pq2, 256, 256, bl1);
    k_aggB<<<(NN * 32 + 255) / 256, 256>>>(bl2);
    // layer 3
    k_tgemm<<<dim3(1, 391), 256>>>((const float*)p_h2, (const float*)p_wc3,
                                   (float*)p_pq3, 128, 128, (const float*)nullptr);
    k_aggC<<<(NN * 16 + 255) / 256, 256>>>(bl3);

    // map encoder
    k_conv1<<<(256 * 1573 + 255) / 256, 256>>>(mapd, k1, cb1);
    k_conv2<<<128, 128>>>(k2, cb2);
    k_wm<<<dim3(64, 8), 256>>>(Wm);
    k_mnorm<<<1, 64>>>(bm);

    // normalize + combine + head
    k_hred1<<<1024, 256>>>();
    k_hred2<<<1, 1024>>>();
    k_xn<<<(NN * 16 + 255) / 256, 256>>>();
    k_tgemm<<<dim3(1, 391), 256>>>((const float*)p_xn, (const float*)p_w1p,
                                   (float*)p_y1, 128, 64, (const float*)nullptr);
    k_head<<<(NN + 255) / 256, 256>>>(W2, b2, b1, out);
}

// round 4
// speedup vs baseline: 2.7496x; 1.6784x over previous
#include <cuda_runtime.h>
#include <mma.h>
#include <math.h>

using namespace nvcuda;

#define NN 50000
#define MP 50048   // padded rows: 391 * 128
#define NE 800000
#define NB1 196    // ceil(NN/256)

// ---------------- scratch ----------------
static __device__ int   d_cnt[NN];
static __device__ int   d_rowptr[NN + 1];
static __device__ int   d_cursor[NN];
static __device__ int   d_csrc[NE];
static __device__ int   d_part[256];
static __device__ float d_xp[(size_t)NN * 32];
static __device__ float d_mx[(size_t)MP * 48];
static __device__ float d_wc1[256 * 48];
static __device__ float d_h1[(size_t)MP * 256];
static __device__ float d_wc2[256 * 256];
static __device__ float d_pq2[(size_t)MP * 256];  // [p(128)|q(128)]
static __device__ float d_h2[(size_t)MP * 128];
static __device__ float d_wc3[128 * 128];
static __device__ float d_pq3[(size_t)MP * 128];  // [p(64)|q(64)]
static __device__ float d_h3[(size_t)MP * 64];
static __device__ float d_w1p[128 * 64];
static __device__ float d_y1[(size_t)MP * 128];
static __device__ float d_m1[256 * 13 * 11 * 11];
static __device__ float d_xcol[(size_t)896 * 6912];
static __device__ float d_cg[896 * 128];
static __device__ float d_m2[128 * 891];
static __device__ float d_mvec[64];
static __device__ float d_mnorm[64];
static __device__ float d_pmin[256];
static __device__ float d_pmax[256];
static __device__ float d_hstats[4];

// ---------------- merged weight packing ----------------
// [0,12288): wc1   [12288,77824): wc2   [77824,94208): wc3   [94208,102400): w1p
__global__ void k_packAll(const float* __restrict__ Wl1, const float* __restrict__ Wr1,
                          const float* __restrict__ Wl2, const float* __restrict__ Wr2,
                          const float* __restrict__ Wl3, const float* __restrict__ Wr3,
                          const float* __restrict__ W1) {
    int i = blockIdx.x * blockDim.x + threadIdx.x;
    if (i < 12288) {
        int n = i / 48, f = i % 48;
        float v = 0.f;
        if (f < 21) v = Wl1[n * 21 + f];
        else if (f < 42) v = Wr1[n * 21 + (f - 21)];
        d_wc1[i] = v;
    } else if (i < 77824) {
        int j = i - 12288;
        int n = j / 256, f = j % 256;
        d_wc2[j] = (n < 128) ? Wl2[n * 256 + f] : Wr2[(n - 128) * 256 + f];
    } else if (i < 94208) {
        int j = i - 77824;
        int n = j / 128, f = j % 128;
        d_wc3[j] = (n < 64) ? Wl3[n * 128 + f] : Wr3[(n - 64) * 128 + f];
    } else if (i < 102400) {
        int j = i - 94208;
        int n = j / 64;
        d_w1p[j] = (n < 64) ? W1[j] : 0.f;
    }
}

// ---------------- CSR build ----------------
__global__ void k_degcnt(const int* __restrict__ ei) {
    int e = blockIdx.x * blockDim.x + threadIdx.x;
    if (e < NE) atomicAdd(&d_cnt[ei[NE + e]], 1);
}
__global__ void k_scan1() {
    __shared__ int sh[256];
    int t = threadIdx.x;
    int i = blockIdx.x * 256 + t;
    int v = (i < NN) ? d_cnt[i] : 0;
    sh[t] = v;
    __syncthreads();
#pragma unroll
    for (int off = 1; off < 256; off <<= 1) {
        int a = (t >= off) ? sh[t - off] : 0;
        __syncthreads();
        sh[t] += a;
        __syncthreads();
    }
    if (i < NN) d_rowptr[i] = sh[t] - v;
    if (t == 255) d_part[blockIdx.x] = sh[255];
}
__global__ void k_scan2() {
    __shared__ int sh[256];
    int t = threadIdx.x;
    int v = (t < NB1) ? d_part[t] : 0;
    sh[t] = v;
    __syncthreads();
#pragma unroll
    for (int off = 1; off < 256; off <<= 1) {
        int a = (t >= off) ? sh[t - off] : 0;
        __syncthreads();
        sh[t] += a;
        __syncthreads();
    }
    if (t < NB1) d_part[t] = sh[t] - v;
}
__global__ void k_scan3() {
    int i = blockIdx.x * 256 + threadIdx.x;
    if (i < NN) {
        int r = d_rowptr[i] + d_part[blockIdx.x];
        d_rowptr[i] = r;
        d_cursor[i] = r;
    }
    if (i == 0) d_rowptr[NN] = NE;
}
__global__ void k_scatter(const int* __restrict__ ei) {
    int e = blockIdx.x * blockDim.x + threadIdx.x;
    if (e >= NE) return;
    int s = ei[e], d = ei[NE + e];
    int pos = atomicAdd(&d_cursor[d], 1);
    d_csrc[pos] = s;
}

// ---------------- node feature pad + aggregation ----------------
__global__ void k_xpad(const float* __restrict__ x) {
    int idx = blockIdx.x * blockDim.x + threadIdx.x;
    if (idx >= NN * 32) return;
    int n = idx >> 5, f = idx & 31;
    d_xp[idx] = (f < 21) ? x[n * 21 + f] : 0.f;
}
__global__ void k_aggA() {
    int w = (blockIdx.x * blockDim.x + threadIdx.x) >> 5;
    int lane = threadIdx.x & 31;
    if (w >= NN) return;
    int beg = d_rowptr[w], end = d_rowptr[w + 1];
    float acc = 0.f;
    for (int e0 = beg; e0 < end; e0 += 32) {
        int cnt = min(32, end - e0);
        int idx = (e0 + lane < end) ? d_csrc[e0 + lane] : 0;
        for (int j = 0; j < cnt; j++) {
            int s = __shfl_sync(0xffffffffu, idx, j);
            acc += d_xp[(size_t)s * 32 + lane];
        }
    }
    float inv = 1.f / fmaxf((float)(end - beg), 1.0f);
    if (lane < 21) {
        d_mx[(size_t)w * 48 + lane] = acc * inv;
        d_mx[(size_t)w * 48 + 21 + lane] = d_xp[(size_t)w * 32 + lane];
    } else if (lane < 27) {
        d_mx[(size_t)w * 48 + 21 + lane] = 0.f;
    }
}
__global__ void k_aggB(const float* __restrict__ bl) {
    int w = (blockIdx.x * blockDim.x + threadIdx.x) >> 5;
    int lane = threadIdx.x & 31;
    if (w >= NN) return;
    int beg = d_rowptr[w], end = d_rowptr[w + 1];
    const float4* pq = (const float4*)d_pq2;
    float4 acc = make_float4(0.f, 0.f, 0.f, 0.f);
#pragma unroll 4
    for (int e = beg; e < end; e++) {
        int s = __ldg(&d_csrc[e]);
        float4 v = pq[(size_t)s * 64 + lane];
        acc.x += v.x; acc.y += v.y; acc.z += v.z; acc.w += v.w;
    }
    float inv = 1.f / fmaxf((float)(end - beg), 1.0f);
    float4 q = pq[(size_t)w * 64 + 32 + lane];
    float4 b = ((const float4*)bl)[lane];
    float4 o;
    o.x = fmaxf(acc.x * inv + b.x + q.x, 0.f);
    o.y = fmaxf(acc.y * inv + b.y + q.y, 0.f);
    o.z = fmaxf(acc.z * inv + b.z + q.z, 0.f);
    o.w = fmaxf(acc.w * inv + b.w + q.w, 0.f);
    ((float4*)d_h2)[(size_t)w * 32 + lane] = o;
}
__global__ void k_aggC(const float* __restrict__ bl) {
    int g = (blockIdx.x * blockDim.x + threadIdx.x) >> 4;
    int lane = threadIdx.x & 15;
    if (g >= NN) return;
    int beg = d_rowptr[g], end = d_rowptr[g + 1];
    const float4* pq = (const float4*)d_pq3;
    float4 acc = make_float4(0.f, 0.f, 0.f, 0.f);
#pragma unroll 4
    for (int e = beg; e < end; e++) {
        int s = __ldg(&d_csrc[e]);
        float4 v = pq[(size_t)s * 32 + lane];
        acc.x += v.x; acc.y += v.y; acc.z += v.z; acc.w += v.w;
    }
    float inv = 1.f / fmaxf((float)(end - beg), 1.0f);
    float4 q = pq[(size_t)g * 32 + 16 + lane];
    float4 b = ((const float4*)bl)[lane];
    float4 o;
    o.x = acc.x * inv + b.x + q.x;
    o.y = acc.y * inv + b.y + q.y;
    o.z = acc.z * inv + b.z + q.z;
    o.w = acc.w * inv + b.w + q.w;
    ((float4*)d_h3)[(size_t)g * 16 + lane] = o;
}

// ---------------- tf32 tensor-core GEMM (double-buffered, optional split-K) ----
// C[.,N] = A[.,K] @ B[N,K]^T.
// A-prolog mode 1 (abias):  a <- relu(a + abias[k])
// A-prolog mode 2 (xstats): a <- hs0*a + hs1 + madd[k]
// split=1: K chunked over gridDim.z, atomicAdd epilogue (C must be pre-zeroed).
__global__ void __launch_bounds__(256) k_tgemm(
    const float* __restrict__ A, const float* __restrict__ B, float* __restrict__ C,
    int N, int K, const float* __restrict__ abias,
    const float* __restrict__ xstats, const float* __restrict__ madd, int split) {
    __shared__ float As[2][128][20];
    __shared__ float Bs[2][128][20];
    int tid = threadIdx.x;
    int wid = tid >> 5;
    int lane = tid & 31;
    int bm = blockIdx.y * 128;
    int bn = blockIdx.x * 128;
    int wm = (wid >> 2) * 64;
    int wn = (wid & 3) * 32;
    int lrow = tid >> 1;
    int lcol = (tid & 1) * 8;
    int nkz = (K / 16) / gridDim.z;
    int kbase = blockIdx.z * nkz * 16;

    float hs0 = 0.f, hs1 = 0.f;
    if (xstats) { hs0 = xstats[0]; hs1 = xstats[1]; }

    wmma::fragment<wmma::accumulator, 16, 16, 8, float> cf[4][2];
#pragma unroll
    for (int i = 0; i < 4; i++)
#pragma unroll
        for (int j = 0; j < 2; j++) wmma::fill_fragment(cf[i][j], 0.f);

    const float* Arow = A + (size_t)(bm + lrow) * K + kbase + lcol;
    const float* Brow = B + (size_t)(bn + lrow) * K + kbase + lcol;

    float4 a0, a1, b0v, b1v;

#define LOADTILE(koff)                                                          \
    do {                                                                        \
        a0 = *(const float4*)(Arow + (koff));                                   \
        a1 = *(const float4*)(Arow + (koff) + 4);                               \
        b0v = *(const float4*)(Brow + (koff));                                  \
        b1v = *(const float4*)(Brow + (koff) + 4);                              \
        if (abias) {                                                            \
            const float* bp = abias + (koff) + lcol;                            \
            a0.x = fmaxf(a0.x + bp[0], 0.f); a0.y = fmaxf(a0.y + bp[1], 0.f);   \
            a0.z = fmaxf(a0.z + bp[2], 0.f); a0.w = fmaxf(a0.w + bp[3], 0.f);   \
            a1.x = fmaxf(a1.x + bp[4], 0.f); a1.y = fmaxf(a1.y + bp[5], 0.f);   \
            a1.z = fmaxf(a1.z + bp[6], 0.f); a1.w = fmaxf(a1.w + bp[7], 0.f);   \
        } else if (xstats) {                                                    \
            const float* mp = madd + (koff) + lcol;                             \
            a0.x = hs0 * a0.x + hs1 + mp[0]; a0.y = hs0 * a0.y + hs1 + mp[1];   \
            a0.z = hs0 * a0.z + hs1 + mp[2]; a0.w = hs0 * a0.w + hs1 + mp[3];   \
            a1.x = hs0 * a1.x + hs1 + mp[4]; a1.y = hs0 * a1.y + hs1 + mp[5];   \
            a1.z = hs0 * a1.z + hs1 + mp[6]; a1.w = hs0 * a1.w + hs1 + mp[7];   \
        }                                                                       \
    } while (0)

#define STORETILE(bi)                                                           \
    do {                                                                        \
        *(float4*)&As[bi][lrow][lcol] = a0;                                     \
        *(float4*)&As[bi][lrow][lcol + 4] = a1;                                 \
        *(float4*)&Bs[bi][lrow][lcol] = b0v;                                    \
        *(float4*)&Bs[bi][lrow][lcol + 4] = b1v;                                \
    } while (0)

    LOADTILE(0);
    STORETILE(0);
    __syncthreads();

    for (int it = 0; it < nkz; it++) {
        int buf = it & 1;
        bool more = (it + 1) < nkz;
        if (more) LOADTILE((it + 1) * 16);
#pragma unroll
        for (int ks = 0; ks < 16; ks += 8) {
            wmma::fragment<wmma::matrix_a, 16, 16, 8, wmma::precision::tf32, wmma::row_major> af[4];
            wmma::fragment<wmma::matrix_b, 16, 16, 8, wmma::precision::tf32, wmma::col_major> bf[2];
#pragma unroll
            for (int i = 0; i < 4; i++) {
                wmma::load_matrix_sync(af[i], &As[buf][wm + i * 16][ks], 20);
#pragma unroll
                for (int t = 0; t < af[i].num_elements; t++)
                    af[i].x[t] = wmma::__float_to_tf32(af[i].x[t]);
            }
#pragma unroll
            for (int j = 0; j < 2; j++) {
                wmma::load_matrix_sync(bf[j], &Bs[buf][wn + j * 16][ks], 20);
#pragma unroll
                for (int t = 0; t < bf[j].num_elements; t++)
                    bf[j].x[t] = wmma::__float_to_tf32(bf[j].x[t]);
            }
#pragma unroll
            for (int i = 0; i < 4; i++)
#pragma unroll
                for (int j = 0; j < 2; j++)
                    wmma::mma_sync(cf[i][j], af[i], bf[j], cf[i][j]);
        }
        if (more) STORETILE(1 - buf);
        __syncthreads();
    }

    if (!split) {
#pragma unroll
        for (int i = 0; i < 4; i++)
#pragma unroll
            for (int j = 0; j < 2; j++)
                wmma::store_matrix_sync(&C[(size_t)(bm + wm + i * 16) * N + bn + wn + j * 16],
                                        cf[i][j], N, wmma::mem_row_major);
    } else {
        // atomic epilogue, staged through reused As smem (warp-private 16x20 slab)
        float* stage = &As[0][0][0] + wid * 320;
#pragma unroll
        for (int i = 0; i < 4; i++)
#pragma unroll
            for (int j = 0; j < 2; j++) {
                wmma::store_matrix_sync(stage, cf[i][j], 20, wmma::mem_row_major);
                __syncwarp();
                float* cp = &C[(size_t)(bm + wm + i * 16) * N + bn + wn + j * 16];
#pragma unroll
                for (int e = 0; e < 8; e++) {
                    int idx = lane * 8 + e;
                    int r = idx >> 4, c = idx & 15;
                    atomicAdd(&cp[(size_t)r * N + c], stage[r * 20 + c]);
                }
                __syncwarp();
            }
    }
#undef LOADTILE
#undef STORETILE
}

// ---------------- map encoder ----------------
__global__ void k_conv1(const float* __restrict__ in, const float* __restrict__ w,
                        const float* __restrict__ b) {
    int idx = blockIdx.x * blockDim.x + threadIdx.x;
    if (idx >= 256 * 1573) return;
    int oc = idx / 1573, p = idx % 1573;
    int od = p / 121, r = p % 121, oh = r / 11, ow = r % 11;
    const float* wp = w + oc * 75;
    float acc = 0.f;
#pragma unroll
    for (int kd = 0; kd < 3; kd++)
#pragma unroll
        for (int kh = 0; kh < 5; kh++)
#pragma unroll
            for (int kw = 0; kw < 5; kw++)
                acc += in[(od + kd) * 225 + (oh + kh) * 15 + (ow + kw)] *
                       wp[kd * 25 + kh * 5 + kw];
    d_m1[idx] = fmaxf(acc + b[oc], 0.f);
}

// im2col: X[pos(891) x (256*27)] from m1[256][13][11][11]
__global__ void k_im2col() {
    int idx = blockIdx.x * blockDim.x + threadIdx.x;
    if (idx >= 891 * 6912) return;
    int pos = idx / 6912, k = idx % 6912;
    int ic = k / 27, tap = k % 27;
    int kd = tap / 9, r = tap % 9, kh = r / 3, kw = r % 3;
    int od = pos / 81, r2 = pos % 81, oh = r2 / 9, ow = r2 % 9;
    d_xcol[(size_t)pos * 6912 + k] =
        d_m1[ic * 1573 + (od + kd) * 121 + (oh + kh) * 11 + (ow + kw)];
}

// transpose conv-gemm result to channel-major + bias + relu
__global__ void k_m2fin(const float* __restrict__ cb2) {
    int idx = blockIdx.x * blockDim.x + threadIdx.x;
    if (idx >= 128 * 891) return;
    int oc = idx / 891, pos = idx % 891;
    d_m2[idx] = fmaxf(d_cg[(size_t)pos * 128 + oc] + cb2[oc], 0.f);
}

__global__ void k_wm(const float* __restrict__ Wm) {
    __shared__ float red[256];
    int o = blockIdx.x;
    int chunk = blockIdx.y;
    const int CH = 114048 / 8;
    int base = chunk * CH;
    const float* wr = Wm + (size_t)o * 114048 + base;
    const float* mv = d_m2 + base;
    float s = 0.f;
    for (int i = threadIdx.x * 4; i < CH; i += 256 * 4) {
        float4 a = *(const float4*)(wr + i);
        float4 v = *(const float4*)(mv + i);
        s += a.x * v.x + a.y * v.y + a.z * v.z + a.w * v.w;
    }
    red[threadIdx.x] = s;
    __syncthreads();
    for (int st = 128; st > 0; st >>= 1) {
        if (threadIdx.x < st) red[threadIdx.x] += red[threadIdx.x + st];
        __syncthreads();
    }
    if (threadIdx.x == 0) atomicAdd(&d_mvec[o], red[0]);
}

// ---------------- h3 min/max ----------------
__global__ void k_hred1() {
    __shared__ float smn[256], smx[256];
    int tid = threadIdx.x;
    float mn = 3.4e38f, mx = -3.4e38f;
    for (size_t i = (size_t)blockIdx.x * 256 + tid; i < (size_t)NN * 64; i += (size_t)256 * 256) {
        float v = d_h3[i];
        mn = fminf(mn, v); mx = fmaxf(mx, v);
    }
    smn[tid] = mn; smx[tid] = mx;
    __syncthreads();
    for (int st = 128; st > 0; st >>= 1) {
        if (tid < st) {
            smn[tid] = fminf(smn[tid], smn[tid + st]);
            smx[tid] = fmaxf(smx[tid], smx[tid + st]);
        }
        __syncthreads();
    }
    if (tid == 0) { d_pmin[blockIdx.x] = smn[0]; d_pmax[blockIdx.x] = smx[0]; }
}
// final stats: h3 min/max -> hstats; mvec+bm min/max -> mnorm
__global__ void k_finstats(const float* __restrict__ bm) {
    __shared__ float smn[256], smx[256];
    int t = threadIdx.x;
    smn[t] = d_pmin[t]; smx[t] = d_pmax[t];
    __syncthreads();
    for (int st = 128; st > 0; st >>= 1) {
        if (t < st) {
            smn[t] = fminf(smn[t], smn[t + st]);
            smx[t] = fmaxf(smx[t], smx[t + st]);
        }
        __syncthreads();
    }
    if (t == 0) {
        float mn = smn[0], mx = smx[0];
        float a = 0.35f / (mx - mn);
        d_hstats[0] = a;
        d_hstats[1] = -mn * a;
    }
    __syncthreads();
    float v = 0.f;
    if (t < 64) v = d_mvec[t] + bm[t];
    smn[t] = (t < 64) ? v : 3.4e38f;
    smx[t] = (t < 64) ? v : -3.4e38f;
    __syncthreads();
    for (int st = 128; st > 0; st >>= 1) {
        if (t < st) {
            smn[t] = fminf(smn[t], smn[t + st]);
            smx[t] = fmaxf(smx[t], smx[t + st]);
        }
        __syncthreads();
    }
    if (t < 64) {
        float mn = smn[0], mx = smx[0];
        d_mnorm[t] = 0.65f * (v - mn) / (mx - mn);
    }
}

// ---------------- final layer + softmax (applies b1 + relu to raw y1) --------
__global__ void k_head(const float* __restrict__ W2, const float* __restrict__ b2,
                       const float* __restrict__ b1, float* __restrict__ out) {
    __shared__ float w2s[3][64];
    __shared__ float b2s[3];
    __shared__ float b1s[64];
    int tid = threadIdx.x;
    if (tid < 192) w2s[tid / 64][tid % 64] = W2[tid];
    if (tid < 3) b2s[tid] = b2[tid];
    if (tid >= 192 && tid < 256) b1s[tid - 192] = b1[tid - 192];
    __syncthreads();
    int i = blockIdx.x * blockDim.x + tid;
    if (i >= NN) return;
    const float* y = d_y1 + (size_t)i * 128;
    float s0 = b2s[0], s1 = b2s[1], s2 = b2s[2];
#pragma unroll
    for (int f = 0; f < 64; f += 4) {
        float4 v = *(const float4*)(y + f);
        v.x = fmaxf(v.x + b1s[f], 0.f);
        v.y = fmaxf(v.y + b1s[f + 1], 0.f);
        v.z = fmaxf(v.z + b1s[f + 2], 0.f);
        v.w = fmaxf(v.w + b1s[f + 3], 0.f);
        s0 += v.x * w2s[0][f] + v.y * w2s[0][f + 1] + v.z * w2s[0][f + 2] + v.w * w2s[0][f + 3];
        s1 += v.x * w2s[1][f] + v.y * w2s[1][f + 1] + v.z * w2s[1][f + 2] + v.w * w2s[1][f + 3];
        s2 += v.x * w2s[2][f] + v.y * w2s[2][f + 1] + v.z * w2s[2][f + 2] + v.w * w2s[2][f + 3];
    }
    float m = fmaxf(s0, fmaxf(s1, s2));
    float e0 = expf(s0 - m), e1 = expf(s1 - m), e2 = expf(s2 - m);
    float inv = 1.f / (e0 + e1 + e2);
    out[(size_t)i * 3 + 0] = e0 * inv;
    out[(size_t)i * 3 + 1] = e1 * inv;
    out[(size_t)i * 3 + 2] = e2 * inv;
}

// ---------------- launch ----------------
extern "C" void kernel_launch(void* const* d_in, const int* in_sizes, int n_in,
                              void* d_out, int out_size) {
    (void)in_sizes; (void)n_in; (void)out_size;
    const float* node = (const float*)d_in[0];
    const int* ei = (const int*)d_in[1];
    const float* mapd = (const float*)d_in[2];
    const float* bl1 = (const float*)d_in[4];
    const float* bl2 = (const float*)d_in[7];
    const float* bl3 = (const float*)d_in[10];
    const float* k1 = (const float*)d_in[12];
    const float* cb1 = (const float*)d_in[13];
    const float* k2 = (const float*)d_in[14];
    const float* cb2 = (const float*)d_in[15];
    const float* Wm = (const float*)d_in[16];
    const float* bm = (const float*)d_in[17];
    const float* b1 = (const float*)d_in[19];
    const float* W2 = (const float*)d_in[20];
    const float* b2 = (const float*)d_in[21];
    float* out = (float*)d_out;

    void *p_cnt, *p_mvec, *p_cg;
    void *p_mx, *p_wc1, *p_h1, *p_wc2, *p_pq2, *p_h2, *p_wc3, *p_pq3, *p_h3;
    void *p_w1p, *p_y1, *p_xcol, *p_hstats, *p_mnorm;
    cudaGetSymbolAddress(&p_cnt, d_cnt);
    cudaGetSymbolAddress(&p_mvec, d_mvec);
    cudaGetSymbolAddress(&p_cg, d_cg);
    cudaGetSymbolAddress(&p_mx, d_mx);
    cudaGetSymbolAddress(&p_wc1, d_wc1);
    cudaGetSymbolAddress(&p_h1, d_h1);
    cudaGetSymbolAddress(&p_wc2, d_wc2);
    cudaGetSymbolAddress(&p_pq2, d_pq2);
    cudaGetSymbolAddress(&p_h2, d_h2);
    cudaGetSymbolAddress(&p_wc3, d_wc3);
    cudaGetSymbolAddress(&p_pq3, d_pq3);
    cudaGetSymbolAddress(&p_h3, d_h3);
    cudaGetSymbolAddress(&p_w1p, d_w1p);
    cudaGetSymbolAddress(&p_y1, d_y1);
    cudaGetSymbolAddress(&p_xcol, d_xcol);
    cudaGetSymbolAddress(&p_hstats, d_hstats);
    cudaGetSymbolAddress(&p_mnorm, d_mnorm);

    // launches 1-3: memsets
    cudaMemsetAsync(p_cnt, 0, NN * sizeof(int));
    cudaMemsetAsync(p_mvec, 0, 64 * sizeof(float));
    cudaMemsetAsync(p_cg, 0, 896 * 128 * sizeof(float));

    // 4: weight packs     5: conv1
    k_packAll<<<400, 256>>>((const float*)d_in[3], (const float*)d_in[5],
                            (const float*)d_in[6], (const float*)d_in[8],
                            (const float*)d_in[9], (const float*)d_in[11],
                            (const float*)d_in[18]);
    k_conv1<<<(256 * 1573 + 255) / 256, 256>>>(mapd, k1, cb1);

    // 6: PROFILING PROBE — small tgemm so ncu (-s 5 -c 1) captures the GEMM
    // inner loop. Writes only to d_y1[0 .. 2048*256), fully overwritten by the
    // real GEMM4 below; final output unchanged.
    k_tgemm<<<dim3(2, 16, 1), 256>>>((const float*)p_h1, (const float*)p_wc2,
                                     (float*)p_y1, 256, 256,
                                     nullptr, nullptr, nullptr, 0);

    // map encoder: im2col + split-K tensor GEMM + finish + Wm GEMV
    k_im2col<<<(891 * 6912 + 255) / 256, 256>>>();
    k_tgemm<<<dim3(1, 7, 8), 256>>>((const float*)p_xcol, k2, (float*)p_cg,
                                    128, 6912, nullptr, nullptr, nullptr, 1);
    k_m2fin<<<(128 * 891 + 255) / 256, 256>>>(cb2);
    k_wm<<<dim3(64, 8), 256>>>(Wm);

    // CSR build
    k_degcnt<<<(NE + 255) / 256, 256>>>(ei);
    k_scan1<<<NB1, 256>>>();
    k_scan2<<<1, 256>>>();
    k_scan3<<<NB1, 256>>>();
    k_scatter<<<(NE + 255) / 256, 256>>>(ei);

    // layer 1
    k_xpad<<<(NN * 32 + 255) / 256, 256>>>(node);
    k_aggA<<<(NN * 32 + 255) / 256, 256>>>();
    k_tgemm<<<dim3(2, 391, 1), 256>>>((const float*)p_mx, (const float*)p_wc1,
                                      (float*)p_h1, 256, 48,
                                      nullptr, nullptr, nullptr, 0);
    // layer 2 (bias+relu of layer1 fused into A-prolog)
    k_tgemm<<<dim3(2, 391, 1), 256>>>((const float*)p_h1, (const float*)p_wc2,
                                      (float*)p_pq2, 256, 256,
                                      bl1, nullptr, nullptr, 0);
    k_aggB<<<(NN * 32 + 255) / 256, 256>>>(bl2);
    // layer 3
    k_tgemm<<<dim3(1, 391, 1), 256>>>((const float*)p_h2, (const float*)p_wc3,
                                      (float*)p_pq3, 128, 128,
                                      nullptr, nullptr, nullptr, 0);
    k_aggC<<<(NN * 16 + 255) / 256, 256>>>(bl3);

    // stats + head (normalization fused into GEMM4 A-prolog)
    k_hred1<<<256, 256>>>();
    k_finstats<<<1, 256>>>(bm);
    k_tgemm<<<dim3(1, 391, 1), 256>>>((const float*)p_h3, (const float*)p_w1p,
                                      (float*)p_y1, 128, 64,
                                      nullptr, (const float*)p_hstats,
                                      (const float*)p_mnorm, 0);
    k_head<<<(NN + 255) / 256, 256>>>(W2, b2, b1, out);
}

// round 5
// speedup vs baseline: 2.8052x; 1.0202x over previous
#include <cuda_runtime.h>
#include <mma.h>
#include <math.h>

using namespace nvcuda;

#define NN 50000
#define MP 50048   // padded rows: 391 * 128
#define NE 800000
#define NB1 196    // ceil(NN/256)

// ---------------- scratch ----------------
static __device__ int   d_cnt[NN];
static __device__ int   d_rowptr[NN + 1];
static __device__ int   d_cursor[NN];
static __device__ int   d_csrc[NE];
static __device__ int   d_part[256];
static __device__ float d_xp[(size_t)NN * 32];
static __device__ float d_mx[(size_t)MP * 48];
static __device__ float d_wc1[256 * 48];
static __device__ float d_h1[(size_t)MP * 256];
static __device__ float d_wc2[256 * 256];
static __device__ float d_pq2[(size_t)MP * 256];  // [p(128)|q(128)]
static __device__ float d_h2[(size_t)MP * 128];
static __device__ float d_wc3[128 * 128];
static __device__ float d_pq3[(size_t)MP * 128];  // [p(64)|q(64)]
static __device__ float d_h3[(size_t)MP * 64];
static __device__ float d_w1p[128 * 64];
static __device__ float d_y1[(size_t)MP * 128];
static __device__ float d_m1[256 * 13 * 11 * 11];
static __device__ float d_xcol[(size_t)896 * 6912];
static __device__ float d_cg[896 * 128];
static __device__ float d_m2[128 * 891];
static __device__ float d_wmpart[8][64];
static __device__ float d_mnorm[64];
static __device__ float d_pmin[256];
static __device__ float d_pmax[256];
static __device__ float d_hstats[4];
static __device__ int   d_koff[6912];
static __device__ int   d_poff[896];

// ---------------- merged weight packing + im2col index tables ----------------
// [0,12288): wc1   [12288,77824): wc2   [77824,94208): wc3   [94208,102400): w1p
// [102400,109312): koff   [109312,110208): poff
__global__ void k_packAll(const float* __restrict__ Wl1, const float* __restrict__ Wr1,
                          const float* __restrict__ Wl2, const float* __restrict__ Wr2,
                          const float* __restrict__ Wl3, const float* __restrict__ Wr3,
                          const float* __restrict__ W1) {
    int i = blockIdx.x * blockDim.x + threadIdx.x;
    if (i < 12288) {
        int n = i / 48, f = i % 48;
        float v = 0.f;
        if (f < 21) v = Wl1[n * 21 + f];
        else if (f < 42) v = Wr1[n * 21 + (f - 21)];
        d_wc1[i] = v;
    } else if (i < 77824) {
        int j = i - 12288;
        int n = j / 256, f = j % 256;
        d_wc2[j] = (n < 128) ? Wl2[n * 256 + f] : Wr2[(n - 128) * 256 + f];
    } else if (i < 94208) {
        int j = i - 77824;
        int n = j / 128, f = j % 128;
        d_wc3[j] = (n < 64) ? Wl3[n * 128 + f] : Wr3[(n - 64) * 128 + f];
    } else if (i < 102400) {
        int j = i - 94208;
        int n = j / 64;
        d_w1p[j] = (n < 64) ? W1[j] : 0.f;
    } else if (i < 109312) {
        int j = i - 102400;
        int ic = j / 27, tap = j % 27;
        int kd = tap / 9, r = tap % 9, kh = r / 3, kw = r % 3;
        d_koff[j] = ic * 1573 + kd * 121 + kh * 11 + kw;
    } else if (i < 110208) {
        int j = i - 109312;
        int v = 0;
        if (j < 891) {
            int od = j / 81, r2 = j % 81, oh = r2 / 9, ow = r2 % 9;
            v = od * 121 + oh * 11 + ow;
        }
        d_poff[j] = v;
    }
}

// ---------------- CSR build ----------------
__global__ void k_degcnt(const int* __restrict__ ei) {
    int e = blockIdx.x * blockDim.x + threadIdx.x;
    if (e < NE) atomicAdd(&d_cnt[ei[NE + e]], 1);
}
__global__ void k_scan1() {
    __shared__ int sh[256];
    int t = threadIdx.x;
    int i = blockIdx.x * 256 + t;
    int v = (i < NN) ? d_cnt[i] : 0;
    sh[t] = v;
    __syncthreads();
#pragma unroll
    for (int off = 1; off < 256; off <<= 1) {
        int a = (t >= off) ? sh[t - off] : 0;
        __syncthreads();
        sh[t] += a;
        __syncthreads();
    }
    if (i < NN) d_rowptr[i] = sh[t] - v;
    if (t == 255) d_part[blockIdx.x] = sh[255];
}
__global__ void k_scan2() {
    __shared__ int sh[256];
    int t = threadIdx.x;
    int v = (t < NB1) ? d_part[t] : 0;
    sh[t] = v;
    __syncthreads();
#pragma unroll
    for (int off = 1; off < 256; off <<= 1) {
        int a = (t >= off) ? sh[t - off] : 0;
        __syncthreads();
        sh[t] += a;
        __syncthreads();
    }
    if (t < NB1) d_part[t] = sh[t] - v;
}
__global__ void k_scan3() {
    int i = blockIdx.x * 256 + threadIdx.x;
    if (i < NN) {
        int r = d_rowptr[i] + d_part[blockIdx.x];
        d_rowptr[i] = r;
        d_cursor[i] = r;
    }
    if (i == 0) d_rowptr[NN] = NE;
}
__global__ void k_scatter(const int* __restrict__ ei) {
    int e = blockIdx.x * blockDim.x + threadIdx.x;
    if (e >= NE) return;
    int s = ei[e], d = ei[NE + e];
    int pos = atomicAdd(&d_cursor[d], 1);
    d_csrc[pos] = s;
}

// ---------------- node feature pad + aggregation ----------------
__global__ void k_xpad(const float* __restrict__ x) {
    int idx = blockIdx.x * blockDim.x + threadIdx.x;
    if (idx >= NN * 32) return;
    int n = idx >> 5, f = idx & 31;
    d_xp[idx] = (f < 21) ? x[n * 21 + f] : 0.f;
}
// warp per node, lane = feature (padded to 32); uniform csrc load, MLP via unroll
__global__ void k_aggA() {
    int w = (blockIdx.x * blockDim.x + threadIdx.x) >> 5;
    int lane = threadIdx.x & 31;
    if (w >= NN) return;
    int beg = d_rowptr[w], end = d_rowptr[w + 1];
    float acc = 0.f;
    int e = beg;
    for (; e + 4 <= end; e += 4) {
        int s0 = __ldg(&d_csrc[e]);
        int s1 = __ldg(&d_csrc[e + 1]);
        int s2 = __ldg(&d_csrc[e + 2]);
        int s3 = __ldg(&d_csrc[e + 3]);
        acc += d_xp[(size_t)s0 * 32 + lane] + d_xp[(size_t)s1 * 32 + lane] +
               d_xp[(size_t)s2 * 32 + lane] + d_xp[(size_t)s3 * 32 + lane];
    }
    for (; e < end; e++) acc += d_xp[(size_t)__ldg(&d_csrc[e]) * 32 + lane];
    float inv = 1.f / fmaxf((float)(end - beg), 1.0f);
    if (lane < 21) {
        d_mx[(size_t)w * 48 + lane] = acc * inv;
        d_mx[(size_t)w * 48 + 21 + lane] = d_xp[(size_t)w * 32 + lane];
    } else if (lane < 27) {
        d_mx[(size_t)w * 48 + 21 + lane] = 0.f;
    }
}
__global__ void k_aggB(const float* __restrict__ bl) {
    int w = (blockIdx.x * blockDim.x + threadIdx.x) >> 5;
    int lane = threadIdx.x & 31;
    if (w >= NN) return;
    int beg = d_rowptr[w], end = d_rowptr[w + 1];
    const float4* pq = (const float4*)d_pq2;
    float4 acc = make_float4(0.f, 0.f, 0.f, 0.f);
#pragma unroll 4
    for (int e = beg; e < end; e++) {
        int s = __ldg(&d_csrc[e]);
        float4 v = pq[(size_t)s * 64 + lane];
        acc.x += v.x; acc.y += v.y; acc.z += v.z; acc.w += v.w;
    }
    float inv = 1.f / fmaxf((float)(end - beg), 1.0f);
    float4 q = pq[(size_t)w * 64 + 32 + lane];
    float4 b = ((const float4*)bl)[lane];
    float4 o;
    o.x = fmaxf(acc.x * inv + b.x + q.x, 0.f);
    o.y = fmaxf(acc.y * inv + b.y + q.y, 0.f);
    o.z = fmaxf(acc.z * inv + b.z + q.z, 0.f);
    o.w = fmaxf(acc.w * inv + b.w + q.w, 0.f);
    ((float4*)d_h2)[(size_t)w * 32 + lane] = o;
}
__global__ void k_aggC(const float* __restrict__ bl) {
    int g = (blockIdx.x * blockDim.x + threadIdx.x) >> 4;
    int lane = threadIdx.x & 15;
    if (g >= NN) return;
    int beg = d_rowptr[g], end = d_rowptr[g + 1];
    const float4* pq = (const float4*)d_pq3;
    float4 acc = make_float4(0.f, 0.f, 0.f, 0.f);
#pragma unroll 4
    for (int e = beg; e < end; e++) {
        int s = __ldg(&d_csrc[e]);
        float4 v = pq[(size_t)s * 32 + lane];
        acc.x += v.x; acc.y += v.y; acc.z += v.z; acc.w += v.w;
    }
    float inv = 1.f / fmaxf((float)(end - beg), 1.0f);
    float4 q = pq[(size_t)g * 32 + 16 + lane];
    float4 b = ((const float4*)bl)[lane];
    float4 o;
    o.x = acc.x * inv + b.x + q.x;
    o.y = acc.y * inv + b.y + q.y;
    o.z = acc.z * inv + b.z + q.z;
    o.w = acc.w * inv + b.w + q.w;
    ((float4*)d_h3)[(size_t)g * 16 + lane] = o;
}

// ---------------- tf32 tensor-core GEMM (double-buffered, optional split-K) ----
__global__ void __launch_bounds__(256) k_tgemm(
    const float* __restrict__ A, const float* __restrict__ B, float* __restrict__ C,
    int N, int K, const float* __restrict__ abias,
    const float* __restrict__ xstats, const float* __restrict__ madd, int split) {
    __shared__ float As[2][128][20];
    __shared__ float Bs[2][128][20];
    int tid = threadIdx.x;
    int wid = tid >> 5;
    int lane = tid & 31;
    int bm = blockIdx.y * 128;
    int bn = blockIdx.x * 128;
    int wm = (wid >> 2) * 64;
    int wn = (wid & 3) * 32;
    int lrow = tid >> 1;
    int lcol = (tid & 1) * 8;
    int nkz = (K / 16) / gridDim.z;
    int kbase = blockIdx.z * nkz * 16;

    float hs0 = 0.f, hs1 = 0.f;
    if (xstats) { hs0 = xstats[0]; hs1 = xstats[1]; }

    wmma::fragment<wmma::accumulator, 16, 16, 8, float> cf[4][2];
#pragma unroll
    for (int i = 0; i < 4; i++)
#pragma unroll
        for (int j = 0; j < 2; j++) wmma::fill_fragment(cf[i][j], 0.f);

    const float* Arow = A + (size_t)(bm + lrow) * K + kbase + lcol;
    const float* Brow = B + (size_t)(bn + lrow) * K + kbase + lcol;

    float4 a0, a1, b0v, b1v;

#define LOADTILE(koff)                                                          \
    do {                                                                        \
        a0 = *(const float4*)(Arow + (koff));                                   \
        a1 = *(const float4*)(Arow + (koff) + 4);                               \
        b0v = *(const float4*)(Brow + (koff));                                  \
        b1v = *(const float4*)(Brow + (koff) + 4);                              \
        if (abias) {                                                            \
            const float* bp = abias + (koff) + lcol;                            \
            a0.x = fmaxf(a0.x + bp[0], 0.f); a0.y = fmaxf(a0.y + bp[1], 0.f);   \
            a0.z = fmaxf(a0.z + bp[2], 0.f); a0.w = fmaxf(a0.w + bp[3], 0.f);   \
            a1.x = fmaxf(a1.x + bp[4], 0.f); a1.y = fmaxf(a1.y + bp[5], 0.f);   \
            a1.z = fmaxf(a1.z + bp[6], 0.f); a1.w = fmaxf(a1.w + bp[7], 0.f);   \
        } else if (xstats) {                                                    \
            const float* mp = madd + (koff) + lcol;                             \
            a0.x = hs0 * a0.x + hs1 + mp[0]; a0.y = hs0 * a0.y + hs1 + mp[1];   \
            a0.z = hs0 * a0.z + hs1 + mp[2]; a0.w = hs0 * a0.w + hs1 + mp[3];   \
            a1.x = hs0 * a1.x + hs1 + mp[4]; a1.y = hs0 * a1.y + hs1 + mp[5];   \
            a1.z = hs0 * a1.z + hs1 + mp[6]; a1.w = hs0 * a1.w + hs1 + mp[7];   \
        }                                                                       \
    } while (0)

#define STORETILE(bi)                                                           \
    do {                                                                        \
        *(float4*)&As[bi][lrow][lcol] = a0;                                     \
        *(float4*)&As[bi][lrow][lcol + 4] = a1;                                 \
        *(float4*)&Bs[bi][lrow][lcol] = b0v;                                    \
        *(float4*)&Bs[bi][lrow][lcol + 4] = b1v;                                \
    } while (0)

    LOADTILE(0);
    STORETILE(0);
    __syncthreads();

    for (int it = 0; it < nkz; it++) {
        int buf = it & 1;
        bool more = (it + 1) < nkz;
        if (more) LOADTILE((it + 1) * 16);
#pragma unroll
        for (int ks = 0; ks < 16; ks += 8) {
            wmma::fragment<wmma::matrix_a, 16, 16, 8, wmma::precision::tf32, wmma::row_major> af[4];
            wmma::fragment<wmma::matrix_b, 16, 16, 8, wmma::precision::tf32, wmma::col_major> bf[2];
#pragma unroll
            for (int i = 0; i < 4; i++) {
                wmma::load_matrix_sync(af[i], &As[buf][wm + i * 16][ks], 20);
#pragma unroll
                for (int t = 0; t < af[i].num_elements; t++)
                    af[i].x[t] = wmma::__float_to_tf32(af[i].x[t]);
            }
#pragma unroll
            for (int j = 0; j < 2; j++) {
                wmma::load_matrix_sync(bf[j], &Bs[buf][wn + j * 16][ks], 20);
#pragma unroll
                for (int t = 0; t < bf[j].num_elements; t++)
                    bf[j].x[t] = wmma::__float_to_tf32(bf[j].x[t]);
            }
#pragma unroll
            for (int i = 0; i < 4; i++)
#pragma unroll
                for (int j = 0; j < 2; j++)
                    wmma::mma_sync(cf[i][j], af[i], bf[j], cf[i][j]);
        }
        if (more) STORETILE(1 - buf);
        __syncthreads();
    }

    if (!split) {
#pragma unroll
        for (int i = 0; i < 4; i++)
#pragma unroll
            for (int j = 0; j < 2; j++)
                wmma::store_matrix_sync(&C[(size_t)(bm + wm + i * 16) * N + bn + wn + j * 16],
                                        cf[i][j], N, wmma::mem_row_major);
    } else {
        float* stage = &As[0][0][0] + wid * 320;
#pragma unroll
        for (int i = 0; i < 4; i++)
#pragma unroll
            for (int j = 0; j < 2; j++) {
                wmma::store_matrix_sync(stage, cf[i][j], 20, wmma::mem_row_major);
                __syncwarp();
                float* cp = &C[(size_t)(bm + wm + i * 16) * N + bn + wn + j * 16];
#pragma unroll
                for (int e = 0; e < 8; e++) {
                    int idx = lane * 8 + e;
                    int r = idx >> 4, c = idx & 15;
                    atomicAdd(&cp[(size_t)r * N + c], stage[r * 20 + c]);
                }
                __syncwarp();
            }
    }
#undef LOADTILE
#undef STORETILE
}

// ---------------- map encoder ----------------
__global__ void k_conv1(const float* __restrict__ in, const float* __restrict__ w,
                        const float* __restrict__ b) {
    int idx = blockIdx.x * blockDim.x + threadIdx.x;
    if (idx >= 256 * 1573) return;
    int oc = idx / 1573, p = idx % 1573;
    int od = p / 121, r = p % 121, oh = r / 11, ow = r % 11;
    const float* wp = w + oc * 75;
    float acc = 0.f;
#pragma unroll
    for (int kd = 0; kd < 3; kd++)
#pragma unroll
        for (int kh = 0; kh < 5; kh++)
#pragma unroll
            for (int kw = 0; kw < 5; kw++)
                acc += in[(od + kd) * 225 + (oh + kh) * 15 + (ow + kw)] *
                       wp[kd * 25 + kh * 5 + kw];
    d_m1[idx] = fmaxf(acc + b[oc], 0.f);
}

// im2col via index tables: grid (27, 891), block 256 — no integer division
__global__ void k_im2col() {
    int k = blockIdx.x * 256 + threadIdx.x;
    int pos = blockIdx.y;
    d_xcol[(size_t)pos * 6912 + k] = d_m1[d_koff[k] + d_poff[pos]];
}

__global__ void k_m2fin(const float* __restrict__ cb2) {
    int idx = blockIdx.x * blockDim.x + threadIdx.x;
    if (idx >= 128 * 891) return;
    int oc = idx / 891, pos = idx % 891;
    d_m2[idx] = fmaxf(d_cg[(size_t)pos * 128 + oc] + cb2[oc], 0.f);
}

// Wm GEMV split-K: partials to d_wmpart (no atomics, no memset)
__global__ void k_wm(const float* __restrict__ Wm) {
    __shared__ float red[256];
    int o = blockIdx.x;
    int chunk = blockIdx.y;
    const int CH = 114048 / 8;
    int base = chunk * CH;
    const float* wr = Wm + (size_t)o * 114048 + base;
    const float* mv = d_m2 + base;
    float s = 0.f;
    for (int i = threadIdx.x * 4; i < CH; i += 256 * 4) {
        float4 a = *(const float4*)(wr + i);
        float4 v = *(const float4*)(mv + i);
        s += a.x * v.x + a.y * v.y + a.z * v.z + a.w * v.w;
    }
    red[threadIdx.x] = s;
    __syncthreads();
    for (int st = 128; st > 0; st >>= 1) {
        if (threadIdx.x < st) red[threadIdx.x] += red[threadIdx.x + st];
        __syncthreads();
    }
    if (threadIdx.x == 0) d_wmpart[chunk][o] = red[0];
}

// ---------------- h3 min/max ----------------
__global__ void k_hred1() {
    __shared__ float smn[256], smx[256];
    int tid = threadIdx.x;
    float mn = 3.4e38f, mx = -3.4e38f;
    for (size_t i = (size_t)blockIdx.x * 256 + tid; i < (size_t)NN * 64; i += (size_t)256 * 256) {
        float v = d_h3[i];
        mn = fminf(mn, v); mx = fmaxf(mx, v);
    }
    smn[tid] = mn; smx[tid] = mx;
    __syncthreads();
    for (int st = 128; st > 0; st >>= 1) {
        if (tid < st) {
            smn[tid] = fminf(smn[tid], smn[tid + st]);
            smx[tid] = fmaxf(smx[tid], smx[tid + st]);
        }
        __syncthreads();
    }
    if (tid == 0) { d_pmin[blockIdx.x] = smn[0]; d_pmax[blockIdx.x] = smx[0]; }
}
__global__ void k_finstats(const float* __restrict__ bm) {
    __shared__ float smn[256], smx[256];
    int t = threadIdx.x;
    smn[t] = d_pmin[t]; smx[t] = d_pmax[t];
    __syncthreads();
    for (int st = 128; st > 0; st >>= 1) {
        if (t < st) {
            smn[t] = fminf(smn[t], smn[t + st]);
            smx[t] = fmaxf(smx[t], smx[t + st]);
        }
        __syncthreads();
    }
    if (t == 0) {
        float mn = smn[0], mx = smx[0];
        float a = 0.35f / (mx - mn);
        d_hstats[0] = a;
        d_hstats[1] = -mn * a;
    }
    __syncthreads();
    float v = 0.f;
    if (t < 64) {
        v = bm[t];
#pragma unroll
        for (int c = 0; c < 8; c++) v += d_wmpart[c][t];
    }
    smn[t] = (t < 64) ? v : 3.4e38f;
    smx[t] = (t < 64) ? v : -3.4e38f;
    __syncthreads();
    for (int st = 128; st > 0; st >>= 1) {
        if (t < st) {
            smn[t] = fminf(smn[t], smn[t + st]);
            smx[t] = fmaxf(smx[t], smx[t + st]);
        }
        __syncthreads();
    }
    if (t < 64) {
        float mn = smn[0], mx = smx[0];
        d_mnorm[t] = 0.65f * (v - mn) / (mx - mn);
    }
}

// ---------------- final layer + softmax ----------------
__global__ void k_head(const float* __restrict__ W2, const float* __restrict__ b2,
                       const float* __restrict__ b1, float* __restrict__ out) {
    __shared__ float w2s[3][64];
    __shared__ float b2s[3];
    __shared__ float b1s[64];
    int tid = threadIdx.x;
    if (tid < 192) w2s[tid / 64][tid % 64] = W2[tid];
    if (tid < 3) b2s[tid] = b2[tid];
    if (tid >= 192 && tid < 256) b1s[tid - 192] = b1[tid - 192];
    __syncthreads();
    int i = blockIdx.x * blockDim.x + tid;
    if (i >= NN) return;
    const float* y = d_y1 + (size_t)i * 128;
    float s0 = b2s[0], s1 = b2s[1], s2 = b2s[2];
#pragma unroll
    for (int f = 0; f < 64; f += 4) {
        float4 v = *(const float4*)(y + f);
        v.x = fmaxf(v.x + b1s[f], 0.f);
        v.y = fmaxf(v.y + b1s[f + 1], 0.f);
        v.z = fmaxf(v.z + b1s[f + 2], 0.f);
        v.w = fmaxf(v.w + b1s[f + 3], 0.f);
        s0 += v.x * w2s[0][f] + v.y * w2s[0][f + 1] + v.z * w2s[0][f + 2] + v.w * w2s[0][f + 3];
        s1 += v.x * w2s[1][f] + v.y * w2s[1][f + 1] + v.z * w2s[1][f + 2] + v.w * w2s[1][f + 3];
        s2 += v.x * w2s[2][f] + v.y * w2s[2][f + 1] + v.z * w2s[2][f + 2] + v.w * w2s[2][f + 3];
    }
    float m = fmaxf(s0, fmaxf(s1, s2));
    float e0 = expf(s0 - m), e1 = expf(s1 - m), e2 = expf(s2 - m);
    float inv = 1.f / (e0 + e1 + e2);
    out[(size_t)i * 3 + 0] = e0 * inv;
    out[(size_t)i * 3 + 1] = e1 * inv;
    out[(size_t)i * 3 + 2] = e2 * inv;
}

// ---------------- launch ----------------
extern "C" void kernel_launch(void* const* d_in, const int* in_sizes, int n_in,
                              void* d_out, int out_size) {
    (void)in_sizes; (void)n_in; (void)out_size;
    const float* node = (const float*)d_in[0];
    const int* ei = (const int*)d_in[1];
    const float* mapd = (const float*)d_in[2];
    const float* bl1 = (const float*)d_in[4];
    const float* bl2 = (const float*)d_in[7];
    const float* bl3 = (const float*)d_in[10];
    const float* k1 = (const float*)d_in[12];
    const float* cb1 = (const float*)d_in[13];
    const float* k2 = (const float*)d_in[14];
    const float* cb2 = (const float*)d_in[15];
    const float* Wm = (const float*)d_in[16];
    const float* bm = (const float*)d_in[17];
    const float* b1 = (const float*)d_in[19];
    const float* W2 = (const float*)d_in[20];
    const float* b2 = (const float*)d_in[21];
    float* out = (float*)d_out;

    void *p_cnt, *p_cg;
    void *p_mx, *p_wc1, *p_h1, *p_wc2, *p_pq2, *p_h2, *p_wc3, *p_pq3, *p_h3;
    void *p_w1p, *p_y1, *p_xcol, *p_hstats, *p_mnorm;
    cudaGetSymbolAddress(&p_cnt, d_cnt);
    cudaGetSymbolAddress(&p_cg, d_cg);
    cudaGetSymbolAddress(&p_mx, d_mx);
    cudaGetSymbolAddress(&p_wc1, d_wc1);
    cudaGetSymbolAddress(&p_h1, d_h1);
    cudaGetSymbolAddress(&p_wc2, d_wc2);
    cudaGetSymbolAddress(&p_pq2, d_pq2);
    cudaGetSymbolAddress(&p_h2, d_h2);
    cudaGetSymbolAddress(&p_wc3, d_wc3);
    cudaGetSymbolAddress(&p_pq3, d_pq3);
    cudaGetSymbolAddress(&p_h3, d_h3);
    cudaGetSymbolAddress(&p_w1p, d_w1p);
    cudaGetSymbolAddress(&p_y1, d_y1);
    cudaGetSymbolAddress(&p_xcol, d_xcol);
    cudaGetSymbolAddress(&p_hstats, d_hstats);
    cudaGetSymbolAddress(&p_mnorm, d_mnorm);

    // counted launches: memset(cnt)=1, memset(cg)=2
    cudaMemsetAsync(p_cnt, 0, NN * sizeof(int));
    cudaMemsetAsync(p_cg, 0, 896 * 128 * sizeof(float));

    // 3: packAll   4: conv1   5: im2col
    k_packAll<<<431, 256>>>((const float*)d_in[3], (const float*)d_in[5],
                            (const float*)d_in[6], (const float*)d_in[8],
                            (const float*)d_in[9], (const float*)d_in[11],
                            (const float*)d_in[18]);
    k_conv1<<<(256 * 1573 + 255) / 256, 256>>>(mapd, k1, cb1);
    k_im2col<<<dim3(27, 891), 256>>>();

    // 6: PROFILING PROBE — GEMM2-shaped tgemm for ncu (-s 5 -c 1).
    // Writes d_y1[0 .. 2048*256), fully overwritten by the real GEMM4 below.
    k_tgemm<<<dim3(2, 16, 1), 256>>>((const float*)p_h1, (const float*)p_wc2,
                                     (float*)p_y1, 256, 256,
                                     nullptr, nullptr, nullptr, 0);

    // conv2 as split-K tensor GEMM + finish + Wm GEMV
    k_tgemm<<<dim3(1, 7, 8), 256>>>((const float*)p_xcol, k2, (float*)p_cg,
                                    128, 6912, nullptr, nullptr, nullptr, 1);
    k_m2fin<<<(128 * 891 + 255) / 256, 256>>>(cb2);
    k_wm<<<dim3(64, 8), 256>>>(Wm);

    // CSR build
    k_degcnt<<<(NE + 255) / 256, 256>>>(ei);
    k_scan1<<<NB1, 256>>>();
    k_scan2<<<1, 256>>>();
    k_scan3<<<NB1, 256>>>();
    k_scatter<<<(NE + 255) / 256, 256>>>(ei);

    // layer 1
    k_xpad<<<(NN * 32 + 255) / 256, 256>>>(node);
    k_aggA<<<(NN * 32 + 255) / 256, 256>>>();
    k_tgemm<<<dim3(2, 391, 1), 256>>>((const float*)p_mx, (const float*)p_wc1,
                                      (float*)p_h1, 256, 48,
                                      nullptr, nullptr, nullptr, 0);
    // layer 2
    k_tgemm<<<dim3(2, 391, 1), 256>>>((const float*)p_h1, (const float*)p_wc2,
                                      (float*)p_pq2, 256, 256,
                                      bl1, nullptr, nullptr, 0);
    k_aggB<<<(NN * 32 + 255) / 256, 256>>>(bl2);
    // layer 3
    k_tgemm<<<dim3(1, 391, 1), 256>>>((const float*)p_h2, (const float*)p_wc3,
                                      (float*)p_pq3, 128, 128,
                                      nullptr, nullptr, nullptr, 0);
    k_aggC<<<(NN * 16 + 255) / 256, 256>>>(bl3);

    // stats + head
    k_hred1<<<256, 256>>>();
    k_finstats<<<1, 256>>>(bm);
    k_tgemm<<<dim3(1, 391, 1), 256>>>((const float*)p_h3, (const float*)p_w1p,
                                      (float*)p_y1, 128, 64,
                                      nullptr, (const float*)p_hstats,
                                      (const float*)p_mnorm, 0);
    k_head<<<(NN + 255) / 256, 256>>>(W2, b2, b1, out);
}

// round 6
// speedup vs baseline: 3.1025x; 1.1060x over previous
#include <cuda_runtime.h>
#include <mma.h>
#include <math.h>

using namespace nvcuda;

#define NN 50000
#define MP 50048   // padded rows: 391 * 128
#define NE 800000
#define NB1 196    // ceil(NN/256)

// ---------------- scratch ----------------
static __device__ int   d_cnt[NN];
static __device__ int   d_rowptr[NN + 1];
static __device__ int   d_cursor[NN];
static __device__ int   d_csrc[NE];
static __device__ int   d_part[256];
static __device__ float d_xp[(size_t)NN * 32];
static __device__ float d_mx[(size_t)MP * 48];
static __device__ float d_wc1[256 * 48];
static __device__ float d_h1[(size_t)MP * 256];
static __device__ float d_wc2[256 * 256];
static __device__ float d_pq2[(size_t)MP * 256];  // [p(128)|q(128)]
static __device__ float d_h2[(size_t)MP * 128];
static __device__ float d_wc3[128 * 128];
static __device__ float d_pq3[(size_t)MP * 128];  // [p(64)|q(64)]
static __device__ float d_h3[(size_t)MP * 64];
static __device__ float d_w1p[128 * 64];
static __device__ float d_y1[(size_t)MP * 128];
static __device__ float d_m1[256 * 13 * 11 * 11];
static __device__ float d_xcol[(size_t)896 * 6912];
static __device__ float d_cg[896 * 128];
static __device__ float d_m2[128 * 891];
static __device__ float d_wmpart[8][64];
static __device__ float d_mnorm[64];
static __device__ float d_pmin[256];
static __device__ float d_pmax[256];
static __device__ float d_hstats[4];
static __device__ int   d_koff[6912];
static __device__ int   d_poff[896];

// ---------------- merged weight packing + im2col index tables ----------------
__global__ void k_packAll(const float* __restrict__ Wl1, const float* __restrict__ Wr1,
                          const float* __restrict__ Wl2, const float* __restrict__ Wr2,
                          const float* __restrict__ Wl3, const float* __restrict__ Wr3,
                          const float* __restrict__ W1) {
    int i = blockIdx.x * blockDim.x + threadIdx.x;
    if (i < 12288) {
        int n = i / 48, f = i % 48;
        float v = 0.f;
        if (f < 21) v = Wl1[n * 21 + f];
        else if (f < 42) v = Wr1[n * 21 + (f - 21)];
        d_wc1[i] = v;
    } else if (i < 77824) {
        int j = i - 12288;
        int n = j / 256, f = j % 256;
        d_wc2[j] = (n < 128) ? Wl2[n * 256 + f] : Wr2[(n - 128) * 256 + f];
    } else if (i < 94208) {
        int j = i - 77824;
        int n = j / 128, f = j % 128;
        d_wc3[j] = (n < 64) ? Wl3[n * 128 + f] : Wr3[(n - 64) * 128 + f];
    } else if (i < 102400) {
        int j = i - 94208;
        int n = j / 64;
        d_w1p[j] = (n < 64) ? W1[j] : 0.f;
    } else if (i < 109312) {
        int j = i - 102400;
        int ic = j / 27, tap = j % 27;
        int kd = tap / 9, r = tap % 9, kh = r / 3, kw = r % 3;
        d_koff[j] = ic * 1573 + kd * 121 + kh * 11 + kw;
    } else if (i < 110208) {
        int j = i - 109312;
        int v = 0;
        if (j < 891) {
            int od = j / 81, r2 = j % 81, oh = r2 / 9, ow = r2 % 9;
            v = od * 121 + oh * 11 + ow;
        }
        d_poff[j] = v;
    }
}

// ---------------- CSR build ----------------
__global__ void k_degcnt(const int* __restrict__ ei) {
    int e = blockIdx.x * blockDim.x + threadIdx.x;
    if (e < NE) atomicAdd(&d_cnt[ei[NE + e]], 1);
}
__global__ void k_scan1() {
    __shared__ int sh[256];
    int t = threadIdx.x;
    int i = blockIdx.x * 256 + t;
    int v = (i < NN) ? d_cnt[i] : 0;
    sh[t] = v;
    __syncthreads();
#pragma unroll
    for (int off = 1; off < 256; off <<= 1) {
        int a = (t >= off) ? sh[t - off] : 0;
        __syncthreads();
        sh[t] += a;
        __syncthreads();
    }
    if (i < NN) d_rowptr[i] = sh[t] - v;  // block-local exclusive
    if (t == 255) d_part[blockIdx.x] = sh[255];
}
// scan of partials folded in: every block prefixes d_part itself (tiny)
__global__ void k_scan3() {
    __shared__ int sh[256];
    int t = threadIdx.x;
    int v = (t < NB1) ? d_part[t] : 0;
    sh[t] = v;
    __syncthreads();
#pragma unroll
    for (int off = 1; off < 256; off <<= 1) {
        int a = (t >= off) ? sh[t - off] : 0;
        __syncthreads();
        sh[t] += a;
        __syncthreads();
    }
    int base = (blockIdx.x > 0) ? sh[blockIdx.x - 1] : 0;  // exclusive prefix
    int i = blockIdx.x * 256 + t;
    if (i < NN) {
        int r = d_rowptr[i] + base;
        d_rowptr[i] = r;
        d_cursor[i] = r;
    }
    if (i == 0) d_rowptr[NN] = NE;
}
__global__ void k_scatter(const int* __restrict__ ei) {
    int e = blockIdx.x * blockDim.x + threadIdx.x;
    if (e >= NE) return;
    int s = ei[e], d = ei[NE + e];
    int pos = atomicAdd(&d_cursor[d], 1);
    d_csrc[pos] = s;
}

// ---------------- node feature pad + aggregation ----------------
__global__ void k_xpad(const float* __restrict__ x) {
    int idx = blockIdx.x * blockDim.x + threadIdx.x;
    if (idx >= NN * 32) return;
    int n = idx >> 5, f = idx & 31;
    d_xp[idx] = (f < 21) ? x[n * 21 + f] : 0.f;
}
__global__ void k_aggA() {
    int w = (blockIdx.x * blockDim.x + threadIdx.x) >> 5;
    int lane = threadIdx.x & 31;
    if (w >= NN) return;
    int beg = d_rowptr[w], end = d_rowptr[w + 1];
    float acc = 0.f;
    int e = beg;
    for (; e + 4 <= end; e += 4) {
        int s0 = __ldg(&d_csrc[e]);
        int s1 = __ldg(&d_csrc[e + 1]);
        int s2 = __ldg(&d_csrc[e + 2]);
        int s3 = __ldg(&d_csrc[e + 3]);
        acc += d_xp[(size_t)s0 * 32 + lane] + d_xp[(size_t)s1 * 32 + lane] +
               d_xp[(size_t)s2 * 32 + lane] + d_xp[(size_t)s3 * 32 + lane];
    }
    for (; e < end; e++) acc += d_xp[(size_t)__ldg(&d_csrc[e]) * 32 + lane];
    float inv = 1.f / fmaxf((float)(end - beg), 1.0f);
    if (lane < 21) {
        d_mx[(size_t)w * 48 + lane] = acc * inv;
        d_mx[(size_t)w * 48 + 21 + lane] = d_xp[(size_t)w * 32 + lane];
    } else if (lane < 27) {
        d_mx[(size_t)w * 48 + 21 + lane] = 0.f;
    }
}
__global__ void k_aggB(const float* __restrict__ bl) {
    int w = (blockIdx.x * blockDim.x + threadIdx.x) >> 5;
    int lane = threadIdx.x & 31;
    if (w >= NN) return;
    int beg = d_rowptr[w], end = d_rowptr[w + 1];
    const float4* pq = (const float4*)d_pq2;
    float4 acc = make_float4(0.f, 0.f, 0.f, 0.f);
#pragma unroll 4
    for (int e = beg; e < end; e++) {
        int s = __ldg(&d_csrc[e]);
        float4 v = pq[(size_t)s * 64 + lane];
        acc.x += v.x; acc.y += v.y; acc.z += v.z; acc.w += v.w;
    }
    float inv = 1.f / fmaxf((float)(end - beg), 1.0f);
    float4 q = pq[(size_t)w * 64 + 32 + lane];
    float4 b = ((const float4*)bl)[lane];
    float4 o;
    o.x = fmaxf(acc.x * inv + b.x + q.x, 0.f);
    o.y = fmaxf(acc.y * inv + b.y + q.y, 0.f);
    o.z = fmaxf(acc.z * inv + b.z + q.z, 0.f);
    o.w = fmaxf(acc.w * inv + b.w + q.w, 0.f);
    ((float4*)d_h2)[(size_t)w * 32 + lane] = o;
}
__global__ void k_aggC(const float* __restrict__ bl) {
    int g = (blockIdx.x * blockDim.x + threadIdx.x) >> 4;
    int lane = threadIdx.x & 15;
    if (g >= NN) return;
    int beg = d_rowptr[g], end = d_rowptr[g + 1];
    const float4* pq = (const float4*)d_pq3;
    float4 acc = make_float4(0.f, 0.f, 0.f, 0.f);
#pragma unroll 4
    for (int e = beg; e < end; e++) {
        int s = __ldg(&d_csrc[e]);
        float4 v = pq[(size_t)s * 32 + lane];
        acc.x += v.x; acc.y += v.y; acc.z += v.z; acc.w += v.w;
    }
    float inv = 1.f / fmaxf((float)(end - beg), 1.0f);
    float4 q = pq[(size_t)g * 32 + 16 + lane];
    float4 b = ((const float4*)bl)[lane];
    float4 o;
    o.x = acc.x * inv + b.x + q.x;
    o.y = acc.y * inv + b.y + q.y;
    o.z = acc.z * inv + b.z + q.z;
    o.w = acc.w * inv + b.w + q.w;
    ((float4*)d_h3)[(size_t)g * 16 + lane] = o;
}

// ---------------- tf32 tensor-core GEMM ----------------
// tf32 conversion happens ONCE at smem store; fragments load-and-go.
__global__ void __launch_bounds__(256, 2) k_tgemm(
    const float* __restrict__ A, const float* __restrict__ B, float* __restrict__ C,
    int N, int K, const float* __restrict__ abias,
    const float* __restrict__ xstats, const float* __restrict__ madd, int split) {
    __shared__ float As[2][128][20];
    __shared__ float Bs[2][128][20];
    int tid = threadIdx.x;
    int wid = tid >> 5;
    int lane = tid & 31;
    int bm = blockIdx.y * 128;
    int bn = blockIdx.x * 128;
    int wm = (wid >> 2) * 64;
    int wn = (wid & 3) * 32;
    int lrow = tid >> 1;
    int lcol = (tid & 1) * 8;
    int nkz = (K / 16) / gridDim.z;
    int kbase = blockIdx.z * nkz * 16;

    float hs0 = 0.f, hs1 = 0.f;
    if (xstats) { hs0 = xstats[0]; hs1 = xstats[1]; }

    wmma::fragment<wmma::accumulator, 16, 16, 8, float> cf[4][2];
#pragma unroll
    for (int i = 0; i < 4; i++)
#pragma unroll
        for (int j = 0; j < 2; j++) wmma::fill_fragment(cf[i][j], 0.f);

    const float* Arow = A + (size_t)(bm + lrow) * K + kbase + lcol;
    const float* Brow = B + (size_t)(bn + lrow) * K + kbase + lcol;

    float4 a0, a1, b0v, b1v;

#define CVT4(v)                                                                 \
    do {                                                                        \
        v.x = wmma::__float_to_tf32(v.x); v.y = wmma::__float_to_tf32(v.y);     \
        v.z = wmma::__float_to_tf32(v.z); v.w = wmma::__float_to_tf32(v.w);     \
    } while (0)

#define LOADTILE(koff)                                                          \
    do {                                                                        \
        a0 = *(const float4*)(Arow + (koff));                                   \
        a1 = *(const float4*)(Arow + (koff) + 4);                               \
        b0v = *(const float4*)(Brow + (koff));                                  \
        b1v = *(const float4*)(Brow + (koff) + 4);                              \
        if (abias) {                                                            \
            const float* bp = abias + (koff) + lcol;                            \
            a0.x = fmaxf(a0.x + bp[0], 0.f); a0.y = fmaxf(a0.y + bp[1], 0.f);   \
            a0.z = fmaxf(a0.z + bp[2], 0.f); a0.w = fmaxf(a0.w + bp[3], 0.f);   \
            a1.x = fmaxf(a1.x + bp[4], 0.f); a1.y = fmaxf(a1.y + bp[5], 0.f);   \
            a1.z = fmaxf(a1.z + bp[6], 0.f); a1.w = fmaxf(a1.w + bp[7], 0.f);   \
        } else if (xstats) {                                                    \
            const float* mp = madd + (koff) + lcol;                             \
            a0.x = hs0 * a0.x + hs1 + mp[0]; a0.y = hs0 * a0.y + hs1 + mp[1];   \
            a0.z = hs0 * a0.z + hs1 + mp[2]; a0.w = hs0 * a0.w + hs1 + mp[3];   \
            a1.x = hs0 * a1.x + hs1 + mp[4]; a1.y = hs0 * a1.y + hs1 + mp[5];   \
            a1.z = hs0 * a1.z + hs1 + mp[6]; a1.w = hs0 * a1.w + hs1 + mp[7];   \
        }                                                                       \
        CVT4(a0); CVT4(a1); CVT4(b0v); CVT4(b1v);                               \
    } while (0)

#define STORETILE(bi)                                                           \
    do {                                                                        \
        *(float4*)&As[bi][lrow][lcol] = a0;                                     \
        *(float4*)&As[bi][lrow][lcol + 4] = a1;                                 \
        *(float4*)&Bs[bi][lrow][lcol] = b0v;                                    \
        *(float4*)&Bs[bi][lrow][lcol + 4] = b1v;                                \
    } while (0)

    LOADTILE(0);
    STORETILE(0);
    __syncthreads();

    for (int it = 0; it < nkz; it++) {
        int buf = it & 1;
        bool more = (it + 1) < nkz;
        if (more) LOADTILE((it + 1) * 16);
#pragma unroll
        for (int ks = 0; ks < 16; ks += 8) {
            wmma::fragment<wmma::matrix_a, 16, 16, 8, wmma::precision::tf32, wmma::row_major> af[4];
            wmma::fragment<wmma::matrix_b, 16, 16, 8, wmma::precision::tf32, wmma::col_major> bf[2];
#pragma unroll
            for (int i = 0; i < 4; i++)
                wmma::load_matrix_sync(af[i], &As[buf][wm + i * 16][ks], 20);
#pragma unroll
            for (int j = 0; j < 2; j++)
                wmma::load_matrix_sync(bf[j], &Bs[buf][wn + j * 16][ks], 20);
#pragma unroll
            for (int i = 0; i < 4; i++)
#pragma unroll
                for (int j = 0; j < 2; j++)
                    wmma::mma_sync(cf[i][j], af[i], bf[j], cf[i][j]);
        }
        if (more) STORETILE(1 - buf);
        __syncthreads();
    }

    if (!split) {
#pragma unroll
        for (int i = 0; i < 4; i++)
#pragma unroll
            for (int j = 0; j < 2; j++)
                wmma::store_matrix_sync(&C[(size_t)(bm + wm + i * 16) * N + bn + wn + j * 16],
                                        cf[i][j], N, wmma::mem_row_major);
    } else {
        float* stage = &As[0][0][0] + wid * 320;
#pragma unroll
        for (int i = 0; i < 4; i++)
#pragma unroll
            for (int j = 0; j < 2; j++) {
                wmma::store_matrix_sync(stage, cf[i][j], 20, wmma::mem_row_major);
                __syncwarp();
                float* cp = &C[(size_t)(bm + wm + i * 16) * N + bn + wn + j * 16];
#pragma unroll
                for (int e = 0; e < 8; e++) {
                    int idx = lane * 8 + e;
                    int r = idx >> 4, c = idx & 15;
                    atomicAdd(&cp[(size_t)r * N + c], stage[r * 20 + c]);
                }
                __syncwarp();
            }
    }
#undef LOADTILE
#undef STORETILE
#undef CVT4
}

// ---------------- map encoder ----------------
__global__ void k_conv1(const float* __restrict__ in, const float* __restrict__ w,
                        const float* __restrict__ b) {
    int idx = blockIdx.x * blockDim.x + threadIdx.x;
    if (idx >= 256 * 1573) return;
    int oc = idx / 1573, p = idx % 1573;
    int od = p / 121, r = p % 121, oh = r / 11, ow = r % 11;
    const float* wp = w + oc * 75;
    float acc = 0.f;
#pragma unroll
    for (int kd = 0; kd < 3; kd++)
#pragma unroll
        for (int kh = 0; kh < 5; kh++)
#pragma unroll
            for (int kw = 0; kw < 5; kw++)
                acc += in[(od + kd) * 225 + (oh + kh) * 15 + (ow + kw)] *
                       wp[kd * 25 + kh * 5 + kw];
    d_m1[idx] = fmaxf(acc + b[oc], 0.f);
}

__global__ void k_im2col() {
    int k = blockIdx.x * 256 + threadIdx.x;
    int pos = blockIdx.y;
    d_xcol[(size_t)pos * 6912 + k] = d_m1[d_koff[k] + d_poff[pos]];
}

__global__ void k_m2fin(const float* __restrict__ cb2) {
    int idx = blockIdx.x * blockDim.x + threadIdx.x;
    if (idx >= 128 * 891) return;
    int oc = idx / 891, pos = idx % 891;
    d_m2[idx] = fmaxf(d_cg[(size_t)pos * 128 + oc] + cb2[oc], 0.f);
}

__global__ void k_wm(const float* __restrict__ Wm) {
    __shared__ float red[256];
    int o = blockIdx.x;
    int chunk = blockIdx.y;
    const int CH = 114048 / 8;
    int base = chunk * CH;
    const float* wr = Wm + (size_t)o * 114048 + base;
    const float* mv = d_m2 + base;
    float s = 0.f;
    for (int i = threadIdx.x * 4; i < CH; i += 256 * 4) {
        float4 a = *(const float4*)(wr + i);
        float4 v = *(const float4*)(mv + i);
        s += a.x * v.x + a.y * v.y + a.z * v.z + a.w * v.w;
    }
    red[threadIdx.x] = s;
    __syncthreads();
    for (int st = 128; st > 0; st >>= 1) {
        if (threadIdx.x < st) red[threadIdx.x] += red[threadIdx.x + st];
        __syncthreads();
    }
    if (threadIdx.x == 0) d_wmpart[chunk][o] = red[0];
}

// ---------------- h3 min/max ----------------
__global__ void k_hred1() {
    __shared__ float smn[256], smx[256];
    int tid = threadIdx.x;
    float mn = 3.4e38f, mx = -3.4e38f;
    for (size_t i = (size_t)blockIdx.x * 256 + tid; i < (size_t)NN * 64; i += (size_t)256 * 256) {
        float v = d_h3[i];
        mn = fminf(mn, v); mx = fmaxf(mx, v);
    }
    smn[tid] = mn; smx[tid] = mx;
    __syncthreads();
    for (int st = 128; st > 0; st >>= 1) {
        if (tid < st) {
            smn[tid] = fminf(smn[tid], smn[tid + st]);
            smx[tid] = fmaxf(smx[tid], smx[tid + st]);
        }
        __syncthreads();
    }
    if (tid == 0) { d_pmin[blockIdx.x] = smn[0]; d_pmax[blockIdx.x] = smx[0]; }
}
__global__ void k_finstats(const float* __restrict__ bm) {
    __shared__ float smn[256], smx[256];
    int t = threadIdx.x;
    smn[t] = d_pmin[t]; smx[t] = d_pmax[t];
    __syncthreads();
    for (int st = 128; st > 0; st >>= 1) {
        if (t < st) {
            smn[t] = fminf(smn[t], smn[t + st]);
            smx[t] = fmaxf(smx[t], smx[t + st]);
        }
        __syncthreads();
    }
    if (t == 0) {
        float mn = smn[0], mx = smx[0];
        float a = 0.35f / (mx - mn);
        d_hstats[0] = a;
        d_hstats[1] = -mn * a;
    }
    __syncthreads();
    float v = 0.f;
    if (t < 64) {
        v = bm[t];
#pragma unroll
        for (int c = 0; c < 8; c++) v += d_wmpart[c][t];
    }
    smn[t] = (t < 64) ? v : 3.4e38f;
    smx[t] = (t < 64) ? v : -3.4e38f;
    __syncthreads();
    for (int st = 128; st > 0; st >>= 1) {
        if (t < st) {
            smn[t] = fminf(smn[t], smn[t + st]);
            smx[t] = fmaxf(smx[t], smx[t + st]);
        }
        __syncthreads();
    }
    if (t < 64) {
        float mn = smn[0], mx = smx[0];
        d_mnorm[t] = 0.65f * (v - mn) / (mx - mn);
    }
}

// ---------------- final layer + softmax ----------------
__global__ void k_head(const float* __restrict__ W2, const float* __restrict__ b2,
                       const float* __restrict__ b1, float* __restrict__ out) {
    __shared__ float w2s[3][64];
    __shared__ float b2s[3];
    __shared__ float b1s[64];
    int tid = threadIdx.x;
    if (tid < 192) w2s[tid / 64][tid % 64] = W2[tid];
    if (tid < 3) b2s[tid] = b2[tid];
    if (tid >= 192 && tid < 256) b1s[tid - 192] = b1[tid - 192];
    __syncthreads();
    int i = blockIdx.x * blockDim.x + tid;
    if (i >= NN) return;
    const float* y = d_y1 + (size_t)i * 128;
    float s0 = b2s[0], s1 = b2s[1], s2 = b2s[2];
#pragma unroll
    for (int f = 0; f < 64; f += 4) {
        float4 v = *(const float4*)(y + f);
        v.x = fmaxf(v.x + b1s[f], 0.f);
        v.y = fmaxf(v.y + b1s[f + 1], 0.f);
        v.z = fmaxf(v.z + b1s[f + 2], 0.f);
        v.w = fmaxf(v.w + b1s[f + 3], 0.f);
        s0 += v.x * w2s[0][f] + v.y * w2s[0][f + 1] + v.z * w2s[0][f + 2] + v.w * w2s[0][f + 3];
        s1 += v.x * w2s[1][f] + v.y * w2s[1][f + 1] + v.z * w2s[1][f + 2] + v.w * w2s[1][f + 3];
        s2 += v.x * w2s[2][f] + v.y * w2s[2][f + 1] + v.z * w2s[2][f + 2] + v.w * w2s[2][f + 3];
    }
    float m = fmaxf(s0, fmaxf(s1, s2));
    float e0 = expf(s0 - m), e1 = expf(s1 - m), e2 = expf(s2 - m);
    float inv = 1.f / (e0 + e1 + e2);
    out[(size_t)i * 3 + 0] = e0 * inv;
    out[(size_t)i * 3 + 1] = e1 * inv;
    out[(size_t)i * 3 + 2] = e2 * inv;
}

// ---------------- launch ----------------
extern "C" void kernel_launch(void* const* d_in, const int* in_sizes, int n_in,
                              void* d_out, int out_size) {
    (void)in_sizes; (void)n_in; (void)out_size;
    const float* node = (const float*)d_in[0];
    const int* ei = (const int*)d_in[1];
    const float* mapd = (const float*)d_in[2];
    const float* bl1 = (const float*)d_in[4];
    const float* bl2 = (const float*)d_in[7];
    const float* bl3 = (const float*)d_in[10];
    const float* k1 = (const float*)d_in[12];
    const float* cb1 = (const float*)d_in[13];
    const float* k2 = (const float*)d_in[14];
    const float* cb2 = (const float*)d_in[15];
    const float* Wm = (const float*)d_in[16];
    const float* bm = (const float*)d_in[17];
    const float* b1 = (const float*)d_in[19];
    const float* W2 = (const float*)d_in[20];
    const float* b2 = (const float*)d_in[21];
    float* out = (float*)d_out;

    void *p_cnt, *p_cg;
    void *p_mx, *p_wc1, *p_h1, *p_wc2, *p_pq2, *p_h2, *p_wc3, *p_pq3, *p_h3;
    void *p_w1p, *p_y1, *p_xcol, *p_hstats, *p_mnorm;
    cudaGetSymbolAddress(&p_cnt, d_cnt);
    cudaGetSymbolAddress(&p_cg, d_cg);
    cudaGetSymbolAddress(&p_mx, d_mx);
    cudaGetSymbolAddress(&p_wc1, d_wc1);
    cudaGetSymbolAddress(&p_h1, d_h1);
    cudaGetSymbolAddress(&p_wc2, d_wc2);
    cudaGetSymbolAddress(&p_pq2, d_pq2);
    cudaGetSymbolAddress(&p_h2, d_h2);
    cudaGetSymbolAddress(&p_wc3, d_wc3);
    cudaGetSymbolAddress(&p_pq3, d_pq3);
    cudaGetSymbolAddress(&p_h3, d_h3);
    cudaGetSymbolAddress(&p_w1p, d_w1p);
    cudaGetSymbolAddress(&p_y1, d_y1);
    cudaGetSymbolAddress(&p_xcol, d_xcol);
    cudaGetSymbolAddress(&p_hstats, d_hstats);
    cudaGetSymbolAddress(&p_mnorm, d_mnorm);

    // 1: memset(cnt)  2: memset(cg)
    cudaMemsetAsync(p_cnt, 0, NN * sizeof(int));
    cudaMemsetAsync(p_cg, 0, 896 * 128 * sizeof(float));

    // 3: packAll   4: conv1   5: im2col   6: conv2 tgemm (ncu target, -s 5 -c 1)
    k_packAll<<<431, 256>>>((const float*)d_in[3], (const float*)d_in[5],
                            (const float*)d_in[6], (const float*)d_in[8],
                            (const float*)d_in[9], (const float*)d_in[11],
                            (const float*)d_in[18]);
    k_conv1<<<(256 * 1573 + 255) / 256, 256>>>(mapd, k1, cb1);
    k_im2col<<<dim3(27, 891), 256>>>();
    k_tgemm<<<dim3(1, 7, 16), 256>>>((const float*)p_xcol, k2, (float*)p_cg,
                                     128, 6912, nullptr, nullptr, nullptr, 1);
    k_m2fin<<<(128 * 891 + 255) / 256, 256>>>(cb2);
    k_wm<<<dim3(64, 8), 256>>>(Wm);

    // CSR build
    k_degcnt<<<(NE + 255) / 256, 256>>>(ei);
    k_scan1<<<NB1, 256>>>();
    k_scan3<<<NB1, 256>>>();
    k_scatter<<<(NE + 255) / 256, 256>>>(ei);

    // layer 1
    k_xpad<<<(NN * 32 + 255) / 256, 256>>>(node);
    k_aggA<<<(NN * 32 + 255) / 256, 256>>>();
    k_tgemm<<<dim3(2, 391, 1), 256>>>((const float*)p_mx, (const float*)p_wc1,
                                      (float*)p_h1, 256, 48,
                                      nullptr, nullptr, nullptr, 0);
    // layer 2
    k_tgemm<<<dim3(2, 391, 1), 256>>>((const float*)p_h1, (const float*)p_wc2,
                                      (float*)p_pq2, 256, 256,
                                      bl1, nullptr, nullptr, 0);
    k_aggB<<<(NN * 32 + 255) / 256, 256>>>(bl2);
    // layer 3
    k_tgemm<<<dim3(1, 391, 1), 256>>>((const float*)p_h2, (const float*)p_wc3,
                                      (float*)p_pq3, 128, 128,
                                      nullptr, nullptr, nullptr, 0);
    k_aggC<<<(NN * 16 + 255) / 256, 256>>>(bl3);

    // stats + head
    k_hred1<<<256, 256>>>();
    k_finstats<<<1, 256>>>(bm);
    k_tgemm<<<dim3(1, 391, 1), 256>>>((const float*)p_h3, (const float*)p_w1p,
                                      (float*)p_y1, 128, 64,
                                      nullptr, (const float*)p_hstats,
                                      (const float*)p_mnorm, 0);
    k_head<<<(NN + 255) / 256, 256>>>(W2, b2, b1, out);
}